// round 1
// baseline (speedup 1.0000x reference)
#include <cuda_runtime.h>

#define NN   50000
#define EE   800000
#define IN_F 128
#define OUT_F 64
#define MAPF 64
#define NH   4

// ---------------- scratch (static device globals; no allocation) ----------------
__device__ int   g_count[NN];
__device__ int   g_off[NN + 1];
__device__ int   g_cursor[NN];
__device__ int   g_srcs[EE];
__device__ float g_z[NN * MAPF];           // x @ W_gm + b_gm
__device__ float g_feat[NN * NH * OUT_F];  // x @ W_fc   (row: [h][64])
__device__ float g_el[NN * NH];
__device__ float g_er[NN * NH];
__device__ float g_gate[NN * NH];
__device__ float g_gated[NN * OUT_F];

// ---------------- CSR build ----------------
__global__ void k_zero() {
    int i = blockIdx.x * blockDim.x + threadIdx.x;
    if (i < NN) g_count[i] = 0;
}

__global__ void k_hist(const int* __restrict__ dst) {
    int e = blockIdx.x * blockDim.x + threadIdx.x;
    if (e < EE) atomicAdd(&g_count[dst[e]], 1);
}

// single block, 1024 threads: exclusive scan of g_count -> g_off, g_cursor
__global__ void k_scan() {
    __shared__ int warp_sums[32];
    __shared__ int s_base;
    int t = threadIdx.x, lane = t & 31, wid = t >> 5;
    if (t == 0) s_base = 0;
    __syncthreads();
    for (int base = 0; base < NN; base += 1024) {
        int i = base + t;
        int v = (i < NN) ? g_count[i] : 0;
        int xs = v;
        #pragma unroll
        for (int d = 1; d < 32; d <<= 1) {
            int y = __shfl_up_sync(0xffffffffu, xs, d);
            if (lane >= d) xs += y;
        }
        if (lane == 31) warp_sums[wid] = xs;
        __syncthreads();
        if (wid == 0) {
            int s = warp_sums[lane];
            #pragma unroll
            for (int d = 1; d < 32; d <<= 1) {
                int y = __shfl_up_sync(0xffffffffu, s, d);
                if (lane >= d) s += y;
            }
            warp_sums[lane] = s;
        }
        __syncthreads();
        int warp_off = (wid > 0) ? warp_sums[wid - 1] : 0;
        int excl = s_base + warp_off + xs - v;
        if (i < NN) { g_off[i] = excl; g_cursor[i] = excl; }
        __syncthreads();
        if (t == 1023) s_base = excl + v;
        // next iteration's __syncthreads() publishes s_base before reuse
    }
    __syncthreads();
    if (t == 0) g_off[NN] = s_base;
}

__global__ void k_scatter(const int* __restrict__ src, const int* __restrict__ dst) {
    int e = blockIdx.x * blockDim.x + threadIdx.x;
    if (e < EE) {
        int d = dst[e];
        int p = atomicAdd(&g_cursor[d], 1);
        g_srcs[p] = src[e];
    }
}

// ---------------- GEMM1: z = x@W_gm + b_gm (ntile 0), feat = x@W_fc (ntiles 1..4) -------
// BM=64, BN=64, BK=16, 256 threads, 4x4 per thread
__global__ void k_gemm1(const float* __restrict__ x,
                        const float* __restrict__ Wgm, const float* __restrict__ bgm,
                        const float* __restrict__ Wfc) {
    __shared__ float As[16][68];
    __shared__ float Bs[16][64];
    int t = threadIdx.x;
    int nt = blockIdx.y;
    int rowBase = blockIdx.x * 64;
    const float* W; int ldw, colBase;
    if (nt == 0) { W = Wgm; ldw = 64;  colBase = 0; }
    else         { W = Wfc; ldw = 256; colBase = (nt - 1) * 64; }

    int tx = t & 15, ty = t >> 4;
    float c[4][4];
    #pragma unroll
    for (int i = 0; i < 4; i++)
        #pragma unroll
        for (int j = 0; j < 4; j++) c[i][j] = 0.f;

    int lr = t >> 2, lq = t & 3;       // A loader: row 0..63, k-float4 0..3
    int gr = rowBase + lr; if (gr >= NN) gr = NN - 1;
    int bk = t >> 4, bq = t & 15;      // B loader: k-row 0..15, col-float4 0..15

    for (int kt = 0; kt < 8; kt++) {
        float4 av = *(const float4*)&x[gr * IN_F + kt * 16 + lq * 4];
        float4 bv = *(const float4*)&W[(kt * 16 + bk) * ldw + colBase + bq * 4];
        As[lq * 4 + 0][lr] = av.x;
        As[lq * 4 + 1][lr] = av.y;
        As[lq * 4 + 2][lr] = av.z;
        As[lq * 4 + 3][lr] = av.w;
        *(float4*)&Bs[bk][bq * 4] = bv;
        __syncthreads();
        #pragma unroll
        for (int kk = 0; kk < 16; kk++) {
            float4 a = *(const float4*)&As[kk][ty * 4];
            float4 b = *(const float4*)&Bs[kk][tx * 4];
            float aa[4] = {a.x, a.y, a.z, a.w};
            float bb[4] = {b.x, b.y, b.z, b.w};
            #pragma unroll
            for (int i = 0; i < 4; i++)
                #pragma unroll
                for (int j = 0; j < 4; j++) c[i][j] += aa[i] * bb[j];
        }
        __syncthreads();
    }

    #pragma unroll
    for (int i = 0; i < 4; i++) {
        int r = rowBase + ty * 4 + i;
        if (r < NN) {
            #pragma unroll
            for (int j = 0; j < 4; j++) {
                int col = tx * 4 + j;
                float v = c[i][j];
                if (nt == 0) g_z[r * MAPF + col] = v + bgm[col];
                else         g_feat[r * (NH * OUT_F) + colBase + col] = v;
            }
        }
    }
}

// ---------------- el/er: per-node head dot products ----------------
__global__ void k_elr(const float* __restrict__ al, const float* __restrict__ ar) {
    int w = threadIdx.x >> 5, lane = threadIdx.x & 31;
    int nodeid = blockIdx.x * 8 + w;
    if (nodeid >= NN) return;
    int h1 = lane >> 4, q = lane & 15;
    const float4* f = (const float4*)g_feat;
    float4 f0 = f[nodeid * 64 + lane];
    float4 f1 = f[nodeid * 64 + 32 + lane];
    const float4* al4 = (const float4*)al;
    const float4* ar4 = (const float4*)ar;
    float4 a0 = al4[h1 * 16 + q], a1 = al4[(h1 + 2) * 16 + q];
    float4 r0 = ar4[h1 * 16 + q], r1 = ar4[(h1 + 2) * 16 + q];
    float el0 = f0.x * a0.x + f0.y * a0.y + f0.z * a0.z + f0.w * a0.w;
    float el1 = f1.x * a1.x + f1.y * a1.y + f1.z * a1.z + f1.w * a1.w;
    float er0 = f0.x * r0.x + f0.y * r0.y + f0.z * r0.z + f0.w * r0.w;
    float er1 = f1.x * r1.x + f1.y * r1.y + f1.z * r1.z + f1.w * r1.w;
    #pragma unroll
    for (int d = 8; d >= 1; d >>= 1) {
        el0 += __shfl_down_sync(0xffffffffu, el0, d);
        el1 += __shfl_down_sync(0xffffffffu, el1, d);
        er0 += __shfl_down_sync(0xffffffffu, er0, d);
        er1 += __shfl_down_sync(0xffffffffu, er1, d);
    }
    if ((lane & 15) == 0) {
        g_el[nodeid * 4 + h1]     = el0;
        g_el[nodeid * 4 + h1 + 2] = el1;
        g_er[nodeid * 4 + h1]     = er0;
        g_er[nodeid * 4 + h1 + 2] = er1;
    }
}

// ---------------- agg1: mean_x + max_z + gate (fused), warp per dst node --------------
__global__ void k_agg1(const float* __restrict__ x,
                       const float* __restrict__ Wg, const float* __restrict__ bg) {
    __shared__ float sWg[(2 * IN_F + MAPF) * NH];  // 320*4
    for (int i = threadIdx.x; i < (2 * IN_F + MAPF) * NH; i += blockDim.x) sWg[i] = Wg[i];
    __syncthreads();
    int w = threadIdx.x >> 5, lane = threadIdx.x & 31;
    int d = blockIdx.x * 8 + w;
    if (d >= NN) return;
    int o0 = g_off[d], o1 = g_off[d + 1];
    int deg = o1 - o0;
    float4 s4 = {0.f, 0.f, 0.f, 0.f};
    float2 zm = {-1e30f, -1e30f};
    const float4* x4 = (const float4*)x;
    const float2* z2 = (const float2*)g_z;
    for (int i = o0; i < o1; i++) {
        int s = g_srcs[i];
        float4 xv = x4[s * 32 + lane];
        s4.x += xv.x; s4.y += xv.y; s4.z += xv.z; s4.w += xv.w;
        float2 zv = z2[s * 32 + lane];
        zm.x = fmaxf(zm.x, zv.x); zm.y = fmaxf(zm.y, zv.y);
    }
    float inv = (deg > 0) ? 1.0f / (float)deg : 0.0f;
    float4 mean = {s4.x * inv, s4.y * inv, s4.z * inv, s4.w * inv};
    if (deg == 0) { zm.x = 0.f; zm.y = 0.f; }
    float4 xd = x4[d * 32 + lane];
    float p[4];
    #pragma unroll
    for (int h = 0; h < 4; h++) {
        int r0 = 4 * lane;
        float v = xd.x * sWg[(r0 + 0) * 4 + h] + xd.y * sWg[(r0 + 1) * 4 + h]
                + xd.z * sWg[(r0 + 2) * 4 + h] + xd.w * sWg[(r0 + 3) * 4 + h];
        int r1 = IN_F + 2 * lane;
        v += zm.x * sWg[(r1 + 0) * 4 + h] + zm.y * sWg[(r1 + 1) * 4 + h];
        int r2 = IN_F + MAPF + 4 * lane;
        v += mean.x * sWg[(r2 + 0) * 4 + h] + mean.y * sWg[(r2 + 1) * 4 + h]
           + mean.z * sWg[(r2 + 2) * 4 + h] + mean.w * sWg[(r2 + 3) * 4 + h];
        p[h] = v;
    }
    #pragma unroll
    for (int dd = 16; dd >= 1; dd >>= 1) {
        #pragma unroll
        for (int h = 0; h < 4; h++) p[h] += __shfl_xor_sync(0xffffffffu, p[h], dd);
    }
    if (lane == 0) {
        #pragma unroll
        for (int h = 0; h < 4; h++)
            g_gate[d * 4 + h] = 1.f / (1.f + __expf(-(p[h] + bg[h])));
    }
}

// ---------------- agg2: attention softmax + weighted sum + head gating, warp/node ------
__global__ void k_agg2(const float* __restrict__ bgat) {
    int w = threadIdx.x >> 5, lane = threadIdx.x & 31;
    int d = blockIdx.x * 8 + w;
    if (d >= NN) return;
    int o0 = g_off[d], o1 = g_off[d + 1];
    int deg = o1 - o0;
    const float4* el4p = (const float4*)g_el;
    float4 er4 = ((const float4*)g_er)[d];
    float m0 = -1e30f, m1 = -1e30f, m2 = -1e30f, m3 = -1e30f;
    for (int i = o0; i < o1; i++) {
        int s = g_srcs[i];
        float4 e = el4p[s];
        float e0 = e.x + er4.x, e1 = e.y + er4.y, e2 = e.z + er4.z, e3 = e.w + er4.w;
        e0 = (e0 > 0.f) ? e0 : 0.2f * e0;
        e1 = (e1 > 0.f) ? e1 : 0.2f * e1;
        e2 = (e2 > 0.f) ? e2 : 0.2f * e2;
        e3 = (e3 > 0.f) ? e3 : 0.2f * e3;
        m0 = fmaxf(m0, e0); m1 = fmaxf(m1, e1); m2 = fmaxf(m2, e2); m3 = fmaxf(m3, e3);
    }
    float den0 = 0.f, den1 = 0.f, den2 = 0.f, den3 = 0.f;
    float4 acc0 = {0.f, 0.f, 0.f, 0.f}, acc1 = {0.f, 0.f, 0.f, 0.f};
    int h1 = lane >> 4, q = lane & 15;
    const float4* f4 = (const float4*)g_feat;
    for (int i = o0; i < o1; i++) {
        int s = g_srcs[i];
        float4 e = el4p[s];
        float e0 = e.x + er4.x, e1 = e.y + er4.y, e2 = e.z + er4.z, e3 = e.w + er4.w;
        e0 = (e0 > 0.f) ? e0 : 0.2f * e0;
        e1 = (e1 > 0.f) ? e1 : 0.2f * e1;
        e2 = (e2 > 0.f) ? e2 : 0.2f * e2;
        e3 = (e3 > 0.f) ? e3 : 0.2f * e3;
        float w0 = __expf(e0 - m0), w1 = __expf(e1 - m1);
        float w2 = __expf(e2 - m2), w3 = __expf(e3 - m3);
        den0 += w0; den1 += w1; den2 += w2; den3 += w3;
        float4 fa = f4[s * 64 + lane];
        float4 fb = f4[s * 64 + 32 + lane];
        float wa = (h1 == 0) ? w0 : w1;
        float wb = (h1 == 0) ? w2 : w3;
        acc0.x += wa * fa.x; acc0.y += wa * fa.y; acc0.z += wa * fa.z; acc0.w += wa * fa.w;
        acc1.x += wb * fb.x; acc1.y += wb * fb.y; acc1.z += wb * fb.z; acc1.w += wb * fb.w;
    }
    float4 bga = ((const float4*)bgat)[h1 * 16 + q];
    float4 bgb = ((const float4*)bgat)[(h1 + 2) * 16 + q];
    float4 a0, a1;
    if (deg > 0) {
        float ia = 1.f / ((h1 == 0) ? den0 : den1);
        float ib = 1.f / ((h1 == 0) ? den2 : den3);
        a0.x = acc0.x * ia + bga.x; a0.y = acc0.y * ia + bga.y;
        a0.z = acc0.z * ia + bga.z; a0.w = acc0.w * ia + bga.w;
        a1.x = acc1.x * ib + bgb.x; a1.y = acc1.y * ib + bgb.y;
        a1.z = acc1.z * ib + bgb.z; a1.w = acc1.w * ib + bgb.w;
    } else {
        a0 = bga; a1 = bgb;
    }
    float g0 = g_gate[d * 4 + h1];
    float g1 = g_gate[d * 4 + h1 + 2];
    float4 pp;
    pp.x = g0 * a0.x + g1 * a1.x;
    pp.y = g0 * a0.y + g1 * a1.y;
    pp.z = g0 * a0.z + g1 * a1.z;
    pp.w = g0 * a0.w + g1 * a1.w;
    pp.x += __shfl_xor_sync(0xffffffffu, pp.x, 16);
    pp.y += __shfl_xor_sync(0xffffffffu, pp.y, 16);
    pp.z += __shfl_xor_sync(0xffffffffu, pp.z, 16);
    pp.w += __shfl_xor_sync(0xffffffffu, pp.w, 16);
    pp.x *= 0.25f; pp.y *= 0.25f; pp.z *= 0.25f; pp.w *= 0.25f;
    if (lane < 16) ((float4*)g_gated)[d * 16 + lane] = pp;
}

// ---------------- merge GEMM: out = [x | gated] @ W_merge + b_merge -------------------
__global__ void k_merge(const float* __restrict__ x, const float* __restrict__ Wm,
                        const float* __restrict__ bm, float* __restrict__ out) {
    __shared__ float As[16][68];
    __shared__ float Bs[16][64];
    int t = threadIdx.x;
    int rowBase = blockIdx.x * 64;
    int tx = t & 15, ty = t >> 4;
    float c[4][4];
    #pragma unroll
    for (int i = 0; i < 4; i++)
        #pragma unroll
        for (int j = 0; j < 4; j++) c[i][j] = 0.f;
    int lr = t >> 2, lq = t & 3;
    int gr = rowBase + lr; if (gr >= NN) gr = NN - 1;
    int bk = t >> 4, bq = t & 15;
    for (int kt = 0; kt < 12; kt++) {
        int k0 = kt * 16 + lq * 4;
        float4 av = (k0 < IN_F) ? ((const float4*)x)[gr * 32 + (k0 >> 2)]
                                : ((const float4*)g_gated)[gr * 16 + ((k0 - IN_F) >> 2)];
        float4 bv = *(const float4*)&Wm[(kt * 16 + bk) * 64 + bq * 4];
        As[lq * 4 + 0][lr] = av.x;
        As[lq * 4 + 1][lr] = av.y;
        As[lq * 4 + 2][lr] = av.z;
        As[lq * 4 + 3][lr] = av.w;
        *(float4*)&Bs[bk][bq * 4] = bv;
        __syncthreads();
        #pragma unroll
        for (int kk = 0; kk < 16; kk++) {
            float4 a = *(const float4*)&As[kk][ty * 4];
            float4 b = *(const float4*)&Bs[kk][tx * 4];
            float aa[4] = {a.x, a.y, a.z, a.w};
            float bb[4] = {b.x, b.y, b.z, b.w};
            #pragma unroll
            for (int i = 0; i < 4; i++)
                #pragma unroll
                for (int j = 0; j < 4; j++) c[i][j] += aa[i] * bb[j];
        }
        __syncthreads();
    }
    #pragma unroll
    for (int i = 0; i < 4; i++) {
        int r = rowBase + ty * 4 + i;
        if (r < NN) {
            #pragma unroll
            for (int j = 0; j < 4; j++) {
                int col = tx * 4 + j;
                out[r * OUT_F + col] = c[i][j] + bm[col];
            }
        }
    }
}

// ---------------- launch ----------------
extern "C" void kernel_launch(void* const* d_in, const int* in_sizes, int n_in,
                              void* d_out, int out_size) {
    const float* x      = (const float*)d_in[0];
    const int*   ei     = (const int*)d_in[1];
    const float* W_gm   = (const float*)d_in[2];
    const float* b_gm   = (const float*)d_in[3];
    const float* W_gate = (const float*)d_in[4];
    const float* b_gate = (const float*)d_in[5];
    const float* W_fc   = (const float*)d_in[6];
    const float* attn_l = (const float*)d_in[7];
    const float* attn_r = (const float*)d_in[8];
    const float* b_gat  = (const float*)d_in[9];
    const float* W_mrg  = (const float*)d_in[10];
    const float* b_mrg  = (const float*)d_in[11];
    float* out = (float*)d_out;

    const int* src = ei;
    const int* dst = ei + EE;

    k_zero<<<(NN + 255) / 256, 256>>>();
    k_hist<<<(EE + 255) / 256, 256>>>(dst);
    k_scan<<<1, 1024>>>();
    k_scatter<<<(EE + 255) / 256, 256>>>(src, dst);
    k_gemm1<<<dim3((NN + 63) / 64, 5), 256>>>(x, W_gm, b_gm, W_fc);
    k_elr<<<(NN + 7) / 8, 256>>>(attn_l, attn_r);
    k_agg1<<<(NN + 7) / 8, 256>>>(x, W_gate, b_gate);
    k_agg2<<<(NN + 7) / 8, 256>>>(b_gat);
    k_merge<<<(NN + 63) / 64, 256>>>(x, W_mrg, b_mrg, out);
}

// round 2
// speedup vs baseline: 1.2654x; 1.2654x over previous
#include <cuda_runtime.h>

#define NN   50000
#define EE   800000
#define IN_F 128
#define OUT_F 64
#define MAPF 64
#define NH   4

// ---------------- scratch (static device globals; no allocation) ----------------
__device__ int   g_count[NN];
__device__ int   g_off[NN + 1];
__device__ int   g_cursor[NN];
__device__ int   g_srcs[EE];
__device__ float g_z[NN * MAPF];           // x @ W_gm + b_gm
__device__ float g_feat[NN * NH * OUT_F];  // x @ W_fc   (row: [h][64])
__device__ float g_el[NN * NH];
__device__ float g_er[NN * NH];
__device__ float g_gate[NN * NH];
__device__ float g_gated[NN * OUT_F];

// ---------------- tf32 helpers ----------------
__device__ __forceinline__ unsigned f2tf(float f) {
    unsigned u;
    asm("cvt.rna.tf32.f32 %0, %1;" : "=r"(u) : "f"(f));
    return u;
}
__device__ __forceinline__ void mma8(float* c, unsigned a0, unsigned a1, unsigned a2,
                                     unsigned a3, unsigned b0, unsigned b1) {
    asm volatile(
        "mma.sync.aligned.m16n8k8.row.col.f32.tf32.tf32.f32 "
        "{%0,%1,%2,%3},{%4,%5,%6,%7},{%8,%9},{%0,%1,%2,%3};"
        : "+f"(c[0]), "+f"(c[1]), "+f"(c[2]), "+f"(c[3])
        : "r"(a0), "r"(a1), "r"(a2), "r"(a3), "r"(b0), "r"(b1));
}

// ---------------- CSR build ----------------
__global__ void k_zero() {
    int i = blockIdx.x * blockDim.x + threadIdx.x;
    if (i < NN) g_count[i] = 0;
}

__global__ void k_hist(const int* __restrict__ dst) {
    int e = blockIdx.x * blockDim.x + threadIdx.x;
    if (e < EE) atomicAdd(&g_count[dst[e]], 1);
}

// single block, 1024 threads: exclusive scan of g_count -> g_off, g_cursor
__global__ void k_scan() {
    __shared__ int warp_sums[32];
    __shared__ int s_base;
    int t = threadIdx.x, lane = t & 31, wid = t >> 5;
    if (t == 0) s_base = 0;
    __syncthreads();
    for (int base = 0; base < NN; base += 1024) {
        int i = base + t;
        int v = (i < NN) ? g_count[i] : 0;
        int xs = v;
        #pragma unroll
        for (int d = 1; d < 32; d <<= 1) {
            int y = __shfl_up_sync(0xffffffffu, xs, d);
            if (lane >= d) xs += y;
        }
        if (lane == 31) warp_sums[wid] = xs;
        __syncthreads();
        if (wid == 0) {
            int s = warp_sums[lane];
            #pragma unroll
            for (int d = 1; d < 32; d <<= 1) {
                int y = __shfl_up_sync(0xffffffffu, s, d);
                if (lane >= d) s += y;
            }
            warp_sums[lane] = s;
        }
        __syncthreads();
        int warp_off = (wid > 0) ? warp_sums[wid - 1] : 0;
        int excl = s_base + warp_off + xs - v;
        if (i < NN) { g_off[i] = excl; g_cursor[i] = excl; }
        __syncthreads();
        if (t == 1023) s_base = excl + v;
    }
    __syncthreads();
    if (t == 0) g_off[NN] = s_base;
}

__global__ void k_scatter(const int* __restrict__ src, const int* __restrict__ dst) {
    int e = blockIdx.x * blockDim.x + threadIdx.x;
    if (e < EE) {
        int d = dst[e];
        int p = atomicAdd(&g_cursor[d], 1);
        g_srcs[p] = src[e];
    }
}

// ---------------- GEMM1 (tf32 tensor cores): z (nt=0), feat (nt=1..4) ----------------
// block tile 128x64, 256 threads = 8 warps, warp tile 32x32, BK=16
__global__ void k_gemm1(const float* __restrict__ x,
                        const float* __restrict__ Wgm, const float* __restrict__ bgm,
                        const float* __restrict__ Wfc) {
    __shared__ unsigned As[128][20];   // [m][k], pad 20 -> conflict-free frag loads
    __shared__ unsigned Bs[16][72];    // [k][n], pad 72 -> conflict-free frag loads
    int t = threadIdx.x;
    int nt = blockIdx.y;
    int rowBase = blockIdx.x * 128;
    const float* W; int ldw, colBase;
    if (nt == 0) { W = Wgm; ldw = 64;  colBase = 0; }
    else         { W = Wfc; ldw = 256; colBase = (nt - 1) * 64; }

    int lane = t & 31, wrp = t >> 5;
    int wm = wrp & 3, wn = wrp >> 2;
    int g = lane >> 2, tig = lane & 3;

    float acc[2][4][4];
    #pragma unroll
    for (int mi = 0; mi < 2; mi++)
        #pragma unroll
        for (int ni = 0; ni < 4; ni++)
            #pragma unroll
            for (int q = 0; q < 4; q++) acc[mi][ni][q] = 0.f;

    int ar0 = t >> 2, akq = t & 3;  // A loader: row, k-quad
    int ar1 = ar0 + 64;
    int gr0 = rowBase + ar0; if (gr0 >= NN) gr0 = NN - 1;
    int gr1 = rowBase + ar1; if (gr1 >= NN) gr1 = NN - 1;
    int bk = t >> 4, bq = t & 15;   // B loader

    for (int kt = 0; kt < 8; kt++) {
        float4 a0v = *(const float4*)&x[gr0 * IN_F + kt * 16 + akq * 4];
        float4 a1v = *(const float4*)&x[gr1 * IN_F + kt * 16 + akq * 4];
        float4 bv  = *(const float4*)&W[(kt * 16 + bk) * ldw + colBase + bq * 4];
        uint4 u0 = {f2tf(a0v.x), f2tf(a0v.y), f2tf(a0v.z), f2tf(a0v.w)};
        uint4 u1 = {f2tf(a1v.x), f2tf(a1v.y), f2tf(a1v.z), f2tf(a1v.w)};
        uint4 ub = {f2tf(bv.x),  f2tf(bv.y),  f2tf(bv.z),  f2tf(bv.w)};
        *(uint4*)&As[ar0][akq * 4] = u0;
        *(uint4*)&As[ar1][akq * 4] = u1;
        *(uint4*)&Bs[bk][bq * 4]   = ub;
        __syncthreads();
        #pragma unroll
        for (int ki = 0; ki < 2; ki++) {
            unsigned a[2][4];
            #pragma unroll
            for (int mi = 0; mi < 2; mi++) {
                int rm = wm * 32 + mi * 16;
                a[mi][0] = As[rm + g][ki * 8 + tig];
                a[mi][1] = As[rm + g + 8][ki * 8 + tig];
                a[mi][2] = As[rm + g][ki * 8 + tig + 4];
                a[mi][3] = As[rm + g + 8][ki * 8 + tig + 4];
            }
            #pragma unroll
            for (int ni = 0; ni < 4; ni++) {
                int cn = wn * 32 + ni * 8;
                unsigned b0 = Bs[ki * 8 + tig][cn + g];
                unsigned b1 = Bs[ki * 8 + tig + 4][cn + g];
                mma8(acc[0][ni], a[0][0], a[0][1], a[0][2], a[0][3], b0, b1);
                mma8(acc[1][ni], a[1][0], a[1][1], a[1][2], a[1][3], b0, b1);
            }
        }
        __syncthreads();
    }

    #pragma unroll
    for (int mi = 0; mi < 2; mi++) {
        #pragma unroll
        for (int ni = 0; ni < 4; ni++) {
            int lc = wn * 32 + ni * 8 + tig * 2;
            #pragma unroll
            for (int half = 0; half < 2; half++) {
                int r = rowBase + wm * 32 + mi * 16 + g + half * 8;
                if (r < NN) {
                    float v0 = acc[mi][ni][half * 2 + 0];
                    float v1 = acc[mi][ni][half * 2 + 1];
                    if (nt == 0) {
                        g_z[r * MAPF + lc]     = v0 + bgm[lc];
                        g_z[r * MAPF + lc + 1] = v1 + bgm[lc + 1];
                    } else {
                        g_feat[r * 256 + colBase + lc]     = v0;
                        g_feat[r * 256 + colBase + lc + 1] = v1;
                    }
                }
            }
        }
    }
}

// ---------------- el/er: per-node head dot products ----------------
__global__ void k_elr(const float* __restrict__ al, const float* __restrict__ ar) {
    int w = threadIdx.x >> 5, lane = threadIdx.x & 31;
    int nodeid = blockIdx.x * 8 + w;
    if (nodeid >= NN) return;
    int h1 = lane >> 4, q = lane & 15;
    const float4* f = (const float4*)g_feat;
    float4 f0 = f[nodeid * 64 + lane];
    float4 f1 = f[nodeid * 64 + 32 + lane];
    const float4* al4 = (const float4*)al;
    const float4* ar4 = (const float4*)ar;
    float4 a0 = al4[h1 * 16 + q], a1 = al4[(h1 + 2) * 16 + q];
    float4 r0 = ar4[h1 * 16 + q], r1 = ar4[(h1 + 2) * 16 + q];
    float el0 = f0.x * a0.x + f0.y * a0.y + f0.z * a0.z + f0.w * a0.w;
    float el1 = f1.x * a1.x + f1.y * a1.y + f1.z * a1.z + f1.w * a1.w;
    float er0 = f0.x * r0.x + f0.y * r0.y + f0.z * r0.z + f0.w * r0.w;
    float er1 = f1.x * r1.x + f1.y * r1.y + f1.z * r1.z + f1.w * r1.w;
    #pragma unroll
    for (int d = 8; d >= 1; d >>= 1) {
        el0 += __shfl_down_sync(0xffffffffu, el0, d);
        el1 += __shfl_down_sync(0xffffffffu, el1, d);
        er0 += __shfl_down_sync(0xffffffffu, er0, d);
        er1 += __shfl_down_sync(0xffffffffu, er1, d);
    }
    if ((lane & 15) == 0) {
        g_el[nodeid * 4 + h1]     = el0;
        g_el[nodeid * 4 + h1 + 2] = el1;
        g_er[nodeid * 4 + h1]     = er0;
        g_er[nodeid * 4 + h1 + 2] = er1;
    }
}

// ---------------- agg1: mean_x + max_z + gate (fused), warp per dst node --------------
__global__ void k_agg1(const float* __restrict__ x,
                       const float* __restrict__ Wg, const float* __restrict__ bg) {
    __shared__ float sWg[(2 * IN_F + MAPF) * NH];  // 320*4
    for (int i = threadIdx.x; i < (2 * IN_F + MAPF) * NH; i += blockDim.x) sWg[i] = Wg[i];
    __syncthreads();
    int w = threadIdx.x >> 5, lane = threadIdx.x & 31;
    int d = blockIdx.x * 8 + w;
    if (d >= NN) return;
    int o0 = g_off[d], o1 = g_off[d + 1];
    int deg = o1 - o0;
    float4 s4 = {0.f, 0.f, 0.f, 0.f};
    float2 zm = {-1e30f, -1e30f};
    const float4* x4 = (const float4*)x;
    const float2* z2 = (const float2*)g_z;
    for (int i = o0; i < o1; i++) {
        int s = g_srcs[i];
        float4 xv = x4[s * 32 + lane];
        s4.x += xv.x; s4.y += xv.y; s4.z += xv.z; s4.w += xv.w;
        float2 zv = z2[s * 32 + lane];
        zm.x = fmaxf(zm.x, zv.x); zm.y = fmaxf(zm.y, zv.y);
    }
    float inv = (deg > 0) ? 1.0f / (float)deg : 0.0f;
    float4 mean = {s4.x * inv, s4.y * inv, s4.z * inv, s4.w * inv};
    if (deg == 0) { zm.x = 0.f; zm.y = 0.f; }
    float4 xd = x4[d * 32 + lane];
    float p[4];
    #pragma unroll
    for (int h = 0; h < 4; h++) {
        int r0 = 4 * lane;
        float v = xd.x * sWg[(r0 + 0) * 4 + h] + xd.y * sWg[(r0 + 1) * 4 + h]
                + xd.z * sWg[(r0 + 2) * 4 + h] + xd.w * sWg[(r0 + 3) * 4 + h];
        int r1 = IN_F + 2 * lane;
        v += zm.x * sWg[(r1 + 0) * 4 + h] + zm.y * sWg[(r1 + 1) * 4 + h];
        int r2 = IN_F + MAPF + 4 * lane;
        v += mean.x * sWg[(r2 + 0) * 4 + h] + mean.y * sWg[(r2 + 1) * 4 + h]
           + mean.z * sWg[(r2 + 2) * 4 + h] + mean.w * sWg[(r2 + 3) * 4 + h];
        p[h] = v;
    }
    #pragma unroll
    for (int dd = 16; dd >= 1; dd >>= 1) {
        #pragma unroll
        for (int h = 0; h < 4; h++) p[h] += __shfl_xor_sync(0xffffffffu, p[h], dd);
    }
    if (lane == 0) {
        #pragma unroll
        for (int h = 0; h < 4; h++)
            g_gate[d * 4 + h] = 1.f / (1.f + __expf(-(p[h] + bg[h])));
    }
}

// ---------------- agg2: attention softmax + weighted sum + head gating, warp/node ------
__global__ void k_agg2(const float* __restrict__ bgat) {
    int w = threadIdx.x >> 5, lane = threadIdx.x & 31;
    int d = blockIdx.x * 8 + w;
    if (d >= NN) return;
    int o0 = g_off[d], o1 = g_off[d + 1];
    int deg = o1 - o0;
    const float4* el4p = (const float4*)g_el;
    float4 er4 = ((const float4*)g_er)[d];
    float m0 = -1e30f, m1 = -1e30f, m2 = -1e30f, m3 = -1e30f;
    for (int i = o0; i < o1; i++) {
        int s = g_srcs[i];
        float4 e = el4p[s];
        float e0 = e.x + er4.x, e1 = e.y + er4.y, e2 = e.z + er4.z, e3 = e.w + er4.w;
        e0 = (e0 > 0.f) ? e0 : 0.2f * e0;
        e1 = (e1 > 0.f) ? e1 : 0.2f * e1;
        e2 = (e2 > 0.f) ? e2 : 0.2f * e2;
        e3 = (e3 > 0.f) ? e3 : 0.2f * e3;
        m0 = fmaxf(m0, e0); m1 = fmaxf(m1, e1); m2 = fmaxf(m2, e2); m3 = fmaxf(m3, e3);
    }
    float den0 = 0.f, den1 = 0.f, den2 = 0.f, den3 = 0.f;
    float4 acc0 = {0.f, 0.f, 0.f, 0.f}, acc1 = {0.f, 0.f, 0.f, 0.f};
    int h1 = lane >> 4, q = lane & 15;
    const float4* f4 = (const float4*)g_feat;
    for (int i = o0; i < o1; i++) {
        int s = g_srcs[i];
        float4 e = el4p[s];
        float e0 = e.x + er4.x, e1 = e.y + er4.y, e2 = e.z + er4.z, e3 = e.w + er4.w;
        e0 = (e0 > 0.f) ? e0 : 0.2f * e0;
        e1 = (e1 > 0.f) ? e1 : 0.2f * e1;
        e2 = (e2 > 0.f) ? e2 : 0.2f * e2;
        e3 = (e3 > 0.f) ? e3 : 0.2f * e3;
        float w0 = __expf(e0 - m0), w1 = __expf(e1 - m1);
        float w2 = __expf(e2 - m2), w3 = __expf(e3 - m3);
        den0 += w0; den1 += w1; den2 += w2; den3 += w3;
        float4 fa = f4[s * 64 + lane];
        float4 fb = f4[s * 64 + 32 + lane];
        float wa = (h1 == 0) ? w0 : w1;
        float wb = (h1 == 0) ? w2 : w3;
        acc0.x += wa * fa.x; acc0.y += wa * fa.y; acc0.z += wa * fa.z; acc0.w += wa * fa.w;
        acc1.x += wb * fb.x; acc1.y += wb * fb.y; acc1.z += wb * fb.z; acc1.w += wb * fb.w;
    }
    float4 bga = ((const float4*)bgat)[h1 * 16 + q];
    float4 bgb = ((const float4*)bgat)[(h1 + 2) * 16 + q];
    float4 a0, a1;
    if (deg > 0) {
        float ia = 1.f / ((h1 == 0) ? den0 : den1);
        float ib = 1.f / ((h1 == 0) ? den2 : den3);
        a0.x = acc0.x * ia + bga.x; a0.y = acc0.y * ia + bga.y;
        a0.z = acc0.z * ia + bga.z; a0.w = acc0.w * ia + bga.w;
        a1.x = acc1.x * ib + bgb.x; a1.y = acc1.y * ib + bgb.y;
        a1.z = acc1.z * ib + bgb.z; a1.w = acc1.w * ib + bgb.w;
    } else {
        a0 = bga; a1 = bgb;
    }
    float g0 = g_gate[d * 4 + h1];
    float g1 = g_gate[d * 4 + h1 + 2];
    float4 pp;
    pp.x = g0 * a0.x + g1 * a1.x;
    pp.y = g0 * a0.y + g1 * a1.y;
    pp.z = g0 * a0.z + g1 * a1.z;
    pp.w = g0 * a0.w + g1 * a1.w;
    pp.x += __shfl_xor_sync(0xffffffffu, pp.x, 16);
    pp.y += __shfl_xor_sync(0xffffffffu, pp.y, 16);
    pp.z += __shfl_xor_sync(0xffffffffu, pp.z, 16);
    pp.w += __shfl_xor_sync(0xffffffffu, pp.w, 16);
    pp.x *= 0.25f; pp.y *= 0.25f; pp.z *= 0.25f; pp.w *= 0.25f;
    if (lane < 16) ((float4*)g_gated)[d * 16 + lane] = pp;
}

// ---------------- merge GEMM (tf32): out = [x | gated] @ W_merge + b_merge ------------
__global__ void k_merge(const float* __restrict__ x, const float* __restrict__ Wm,
                        const float* __restrict__ bm, float* __restrict__ out) {
    __shared__ unsigned As[128][20];
    __shared__ unsigned Bs[16][72];
    int t = threadIdx.x;
    int rowBase = blockIdx.x * 128;
    int lane = t & 31, wrp = t >> 5;
    int wm = wrp & 3, wn = wrp >> 2;
    int g = lane >> 2, tig = lane & 3;

    float acc[2][4][4];
    #pragma unroll
    for (int mi = 0; mi < 2; mi++)
        #pragma unroll
        for (int ni = 0; ni < 4; ni++)
            #pragma unroll
            for (int q = 0; q < 4; q++) acc[mi][ni][q] = 0.f;

    int ar0 = t >> 2, akq = t & 3;
    int ar1 = ar0 + 64;
    int gr0 = rowBase + ar0; if (gr0 >= NN) gr0 = NN - 1;
    int gr1 = rowBase + ar1; if (gr1 >= NN) gr1 = NN - 1;
    int bk = t >> 4, bq = t & 15;

    for (int kt = 0; kt < 12; kt++) {
        int k0 = kt * 16 + akq * 4;
        float4 a0v, a1v;
        if (k0 < IN_F) {
            a0v = *(const float4*)&x[gr0 * IN_F + k0];
            a1v = *(const float4*)&x[gr1 * IN_F + k0];
        } else {
            a0v = *(const float4*)&g_gated[gr0 * OUT_F + (k0 - IN_F)];
            a1v = *(const float4*)&g_gated[gr1 * OUT_F + (k0 - IN_F)];
        }
        float4 bv = *(const float4*)&Wm[(kt * 16 + bk) * 64 + bq * 4];
        uint4 u0 = {f2tf(a0v.x), f2tf(a0v.y), f2tf(a0v.z), f2tf(a0v.w)};
        uint4 u1 = {f2tf(a1v.x), f2tf(a1v.y), f2tf(a1v.z), f2tf(a1v.w)};
        uint4 ub = {f2tf(bv.x),  f2tf(bv.y),  f2tf(bv.z),  f2tf(bv.w)};
        *(uint4*)&As[ar0][akq * 4] = u0;
        *(uint4*)&As[ar1][akq * 4] = u1;
        *(uint4*)&Bs[bk][bq * 4]   = ub;
        __syncthreads();
        #pragma unroll
        for (int ki = 0; ki < 2; ki++) {
            unsigned a[2][4];
            #pragma unroll
            for (int mi = 0; mi < 2; mi++) {
                int rm = wm * 32 + mi * 16;
                a[mi][0] = As[rm + g][ki * 8 + tig];
                a[mi][1] = As[rm + g + 8][ki * 8 + tig];
                a[mi][2] = As[rm + g][ki * 8 + tig + 4];
                a[mi][3] = As[rm + g + 8][ki * 8 + tig + 4];
            }
            #pragma unroll
            for (int ni = 0; ni < 4; ni++) {
                int cn = wn * 32 + ni * 8;
                unsigned b0 = Bs[ki * 8 + tig][cn + g];
                unsigned b1 = Bs[ki * 8 + tig + 4][cn + g];
                mma8(acc[0][ni], a[0][0], a[0][1], a[0][2], a[0][3], b0, b1);
                mma8(acc[1][ni], a[1][0], a[1][1], a[1][2], a[1][3], b0, b1);
            }
        }
        __syncthreads();
    }

    #pragma unroll
    for (int mi = 0; mi < 2; mi++) {
        #pragma unroll
        for (int ni = 0; ni < 4; ni++) {
            int lc = wn * 32 + ni * 8 + tig * 2;
            #pragma unroll
            for (int half = 0; half < 2; half++) {
                int r = rowBase + wm * 32 + mi * 16 + g + half * 8;
                if (r < NN) {
                    out[r * OUT_F + lc]     = acc[mi][ni][half * 2 + 0] + bm[lc];
                    out[r * OUT_F + lc + 1] = acc[mi][ni][half * 2 + 1] + bm[lc + 1];
                }
            }
        }
    }
}

// ---------------- launch ----------------
extern "C" void kernel_launch(void* const* d_in, const int* in_sizes, int n_in,
                              void* d_out, int out_size) {
    const float* x      = (const float*)d_in[0];
    const int*   ei     = (const int*)d_in[1];
    const float* W_gm   = (const float*)d_in[2];
    const float* b_gm   = (const float*)d_in[3];
    const float* W_gate = (const float*)d_in[4];
    const float* b_gate = (const float*)d_in[5];
    const float* W_fc   = (const float*)d_in[6];
    const float* attn_l = (const float*)d_in[7];
    const float* attn_r = (const float*)d_in[8];
    const float* b_gat  = (const float*)d_in[9];
    const float* W_mrg  = (const float*)d_in[10];
    const float* b_mrg  = (const float*)d_in[11];
    float* out = (float*)d_out;

    const int* src = ei;
    const int* dst = ei + EE;

    k_zero<<<(NN + 255) / 256, 256>>>();
    k_hist<<<(EE + 255) / 256, 256>>>(dst);
    k_scan<<<1, 1024>>>();
    k_scatter<<<(EE + 255) / 256, 256>>>(src, dst);
    k_gemm1<<<dim3((NN + 127) / 128, 5), 256>>>(x, W_gm, b_gm, W_fc);
    k_elr<<<(NN + 7) / 8, 256>>>(attn_l, attn_r);
    k_agg1<<<(NN + 7) / 8, 256>>>(x, W_gate, b_gate);
    k_agg2<<<(NN + 7) / 8, 256>>>(b_gat);
    k_merge<<<(NN + 127) / 128, 256>>>(x, W_mrg, b_mrg, out);
}

// round 3
// speedup vs baseline: 1.3400x; 1.0589x over previous
#include <cuda_runtime.h>
#include <cuda_fp16.h>

#define NN   50000
#define EE   800000
#define IN_F 128
#define OUT_F 64
#define MAPF 64
#define NH   4

// ---------------- scratch (static device globals; no allocation) ----------------
__device__ int   g_count[NN];
__device__ int   g_off[NN + 1];
__device__ int   g_cursor[NN];
__device__ int   g_srcs[EE];
__device__ uint2    g_xh[NN * 32];   // x  as fp16: 128 halfs/row
__device__ unsigned g_zh[NN * 32];   // z  as fp16: 64 halfs/row
__device__ uint2    g_fh[NN * 64];   // feat as fp16: 256 halfs/row ([h][64])
__device__ float g_el[NN * NH];
__device__ float g_er[NN * NH];
__device__ float g_gated[NN * OUT_F];

// ---------------- helpers ----------------
__device__ __forceinline__ unsigned f2tf(float f) {
    unsigned u;
    asm("cvt.rna.tf32.f32 %0, %1;" : "=r"(u) : "f"(f));
    return u;
}
__device__ __forceinline__ void mma8(float* c, unsigned a0, unsigned a1, unsigned a2,
                                     unsigned a3, unsigned b0, unsigned b1) {
    asm volatile(
        "mma.sync.aligned.m16n8k8.row.col.f32.tf32.tf32.f32 "
        "{%0,%1,%2,%3},{%4,%5,%6,%7},{%8,%9},{%0,%1,%2,%3};"
        : "+f"(c[0]), "+f"(c[1]), "+f"(c[2]), "+f"(c[3])
        : "r"(a0), "r"(a1), "r"(a2), "r"(a3), "r"(b0), "r"(b1));
}
__device__ __forceinline__ unsigned packh2(float a, float b) {
    __half2 h = __floats2half2_rn(a, b);
    return *(unsigned*)&h;
}
__device__ __forceinline__ float2 unpackh2(unsigned u) {
    return __half22float2(*(__half2*)&u);
}

// ---------------- CSR build ----------------
__global__ void k_zero() {
    int i = blockIdx.x * blockDim.x + threadIdx.x;
    if (i < NN) g_count[i] = 0;
}

__global__ void k_hist(const int* __restrict__ dst) {
    int e = blockIdx.x * blockDim.x + threadIdx.x;
    if (e < EE) atomicAdd(&g_count[dst[e]], 1);
}

__global__ void k_scan() {
    __shared__ int warp_sums[32];
    __shared__ int s_base;
    int t = threadIdx.x, lane = t & 31, wid = t >> 5;
    if (t == 0) s_base = 0;
    __syncthreads();
    for (int base = 0; base < NN; base += 1024) {
        int i = base + t;
        int v = (i < NN) ? g_count[i] : 0;
        int xs = v;
        #pragma unroll
        for (int d = 1; d < 32; d <<= 1) {
            int y = __shfl_up_sync(0xffffffffu, xs, d);
            if (lane >= d) xs += y;
        }
        if (lane == 31) warp_sums[wid] = xs;
        __syncthreads();
        if (wid == 0) {
            int s = warp_sums[lane];
            #pragma unroll
            for (int d = 1; d < 32; d <<= 1) {
                int y = __shfl_up_sync(0xffffffffu, s, d);
                if (lane >= d) s += y;
            }
            warp_sums[lane] = s;
        }
        __syncthreads();
        int warp_off = (wid > 0) ? warp_sums[wid - 1] : 0;
        int excl = s_base + warp_off + xs - v;
        if (i < NN) { g_off[i] = excl; g_cursor[i] = excl; }
        __syncthreads();
        if (t == 1023) s_base = excl + v;
    }
    __syncthreads();
    if (t == 0) g_off[NN] = s_base;
}

__global__ void k_scatter(const int* __restrict__ src, const int* __restrict__ dst) {
    int e = blockIdx.x * blockDim.x + threadIdx.x;
    if (e < EE) {
        int d = dst[e];
        int p = atomicAdd(&g_cursor[d], 1);
        g_srcs[p] = src[e];
    }
}

// ---------------- x -> fp16 copy ----------------
__global__ void k_xhalf(const float* __restrict__ x) {
    int i = blockIdx.x * blockDim.x + threadIdx.x;
    if (i < NN * 32) {
        float4 v = ((const float4*)x)[i];
        uint2 u;
        u.x = packh2(v.x, v.y);
        u.y = packh2(v.z, v.w);
        g_xh[i] = u;
    }
}

// ---------------- GEMM1 (tf32): z_h (nt=0), feat_h (nt=1..4) ----------------
__global__ void k_gemm1(const float* __restrict__ x,
                        const float* __restrict__ Wgm, const float* __restrict__ bgm,
                        const float* __restrict__ Wfc) {
    __shared__ unsigned As[128][20];
    __shared__ unsigned Bs[16][72];
    int t = threadIdx.x;
    int nt = blockIdx.y;
    int rowBase = blockIdx.x * 128;
    const float* W; int ldw, colBase;
    if (nt == 0) { W = Wgm; ldw = 64;  colBase = 0; }
    else         { W = Wfc; ldw = 256; colBase = (nt - 1) * 64; }

    int lane = t & 31, wrp = t >> 5;
    int wm = wrp & 3, wn = wrp >> 2;
    int g = lane >> 2, tig = lane & 3;

    float acc[2][4][4];
    #pragma unroll
    for (int mi = 0; mi < 2; mi++)
        #pragma unroll
        for (int ni = 0; ni < 4; ni++)
            #pragma unroll
            for (int q = 0; q < 4; q++) acc[mi][ni][q] = 0.f;

    int ar0 = t >> 2, akq = t & 3;
    int ar1 = ar0 + 64;
    int gr0 = rowBase + ar0; if (gr0 >= NN) gr0 = NN - 1;
    int gr1 = rowBase + ar1; if (gr1 >= NN) gr1 = NN - 1;
    int bk = t >> 4, bq = t & 15;

    for (int kt = 0; kt < 8; kt++) {
        float4 a0v = *(const float4*)&x[gr0 * IN_F + kt * 16 + akq * 4];
        float4 a1v = *(const float4*)&x[gr1 * IN_F + kt * 16 + akq * 4];
        float4 bv  = *(const float4*)&W[(kt * 16 + bk) * ldw + colBase + bq * 4];
        uint4 u0 = {f2tf(a0v.x), f2tf(a0v.y), f2tf(a0v.z), f2tf(a0v.w)};
        uint4 u1 = {f2tf(a1v.x), f2tf(a1v.y), f2tf(a1v.z), f2tf(a1v.w)};
        uint4 ub = {f2tf(bv.x),  f2tf(bv.y),  f2tf(bv.z),  f2tf(bv.w)};
        *(uint4*)&As[ar0][akq * 4] = u0;
        *(uint4*)&As[ar1][akq * 4] = u1;
        *(uint4*)&Bs[bk][bq * 4]   = ub;
        __syncthreads();
        #pragma unroll
        for (int ki = 0; ki < 2; ki++) {
            unsigned a[2][4];
            #pragma unroll
            for (int mi = 0; mi < 2; mi++) {
                int rm = wm * 32 + mi * 16;
                a[mi][0] = As[rm + g][ki * 8 + tig];
                a[mi][1] = As[rm + g + 8][ki * 8 + tig];
                a[mi][2] = As[rm + g][ki * 8 + tig + 4];
                a[mi][3] = As[rm + g + 8][ki * 8 + tig + 4];
            }
            #pragma unroll
            for (int ni = 0; ni < 4; ni++) {
                int cn = wn * 32 + ni * 8;
                unsigned b0 = Bs[ki * 8 + tig][cn + g];
                unsigned b1 = Bs[ki * 8 + tig + 4][cn + g];
                mma8(acc[0][ni], a[0][0], a[0][1], a[0][2], a[0][3], b0, b1);
                mma8(acc[1][ni], a[1][0], a[1][1], a[1][2], a[1][3], b0, b1);
            }
        }
        __syncthreads();
    }

    #pragma unroll
    for (int mi = 0; mi < 2; mi++) {
        #pragma unroll
        for (int ni = 0; ni < 4; ni++) {
            int lc = wn * 32 + ni * 8 + tig * 2;
            #pragma unroll
            for (int half = 0; half < 2; half++) {
                int r = rowBase + wm * 32 + mi * 16 + g + half * 8;
                if (r < NN) {
                    float v0 = acc[mi][ni][half * 2 + 0];
                    float v1 = acc[mi][ni][half * 2 + 1];
                    if (nt == 0) {
                        g_zh[r * 32 + (lc >> 1)] = packh2(v0 + bgm[lc], v1 + bgm[lc + 1]);
                    } else {
                        ((unsigned*)g_fh)[r * 128 + ((colBase + lc) >> 1)] = packh2(v0, v1);
                    }
                }
            }
        }
    }
}

// ---------------- el/er: per-node head dot products (fp16 feat) ----------------
__global__ void k_elr(const float* __restrict__ al, const float* __restrict__ ar) {
    int w = threadIdx.x >> 5, lane = threadIdx.x & 31;
    int nodeid = blockIdx.x * 8 + w;
    if (nodeid >= NN) return;
    int h1 = lane >> 4, q = lane & 15;
    uint2 ua = g_fh[nodeid * 64 + lane];
    uint2 ub = g_fh[nodeid * 64 + 32 + lane];
    float2 fa0 = unpackh2(ua.x), fa1 = unpackh2(ua.y);
    float2 fb0 = unpackh2(ub.x), fb1 = unpackh2(ub.y);
    const float4* al4 = (const float4*)al;
    const float4* ar4 = (const float4*)ar;
    float4 a0 = al4[h1 * 16 + q], a1 = al4[(h1 + 2) * 16 + q];
    float4 r0 = ar4[h1 * 16 + q], r1 = ar4[(h1 + 2) * 16 + q];
    float el0 = fa0.x * a0.x + fa0.y * a0.y + fa1.x * a0.z + fa1.y * a0.w;
    float el1 = fb0.x * a1.x + fb0.y * a1.y + fb1.x * a1.z + fb1.y * a1.w;
    float er0 = fa0.x * r0.x + fa0.y * r0.y + fa1.x * r0.z + fa1.y * r0.w;
    float er1 = fb0.x * r1.x + fb0.y * r1.y + fb1.x * r1.z + fb1.y * r1.w;
    #pragma unroll
    for (int d = 8; d >= 1; d >>= 1) {
        el0 += __shfl_down_sync(0xffffffffu, el0, d);
        el1 += __shfl_down_sync(0xffffffffu, el1, d);
        er0 += __shfl_down_sync(0xffffffffu, er0, d);
        er1 += __shfl_down_sync(0xffffffffu, er1, d);
    }
    if ((lane & 15) == 0) {
        g_el[nodeid * 4 + h1]     = el0;
        g_el[nodeid * 4 + h1 + 2] = el1;
        g_er[nodeid * 4 + h1]     = er0;
        g_er[nodeid * 4 + h1 + 2] = er1;
    }
}

// ---------------- fused agg: mean/max/gate + attention softmax + gated avg ----------
__global__ void k_agg(const float* __restrict__ x,
                      const float* __restrict__ Wg, const float* __restrict__ bg,
                      const float* __restrict__ bgat) {
    __shared__ float sWg[(2 * IN_F + MAPF) * NH];
    for (int i = threadIdx.x; i < (2 * IN_F + MAPF) * NH; i += blockDim.x) sWg[i] = Wg[i];
    __syncthreads();
    int w = threadIdx.x >> 5, lane = threadIdx.x & 31;
    int d = blockIdx.x * 8 + w;
    if (d >= NN) return;
    int o0 = g_off[d], o1 = g_off[d + 1];
    int deg = o1 - o0;

    const float4* el4p = (const float4*)g_el;
    float4 er4 = ((const float4*)g_er)[d];

    // ---- loop A: sum x, max z, max e ----
    float4 s4 = {0.f, 0.f, 0.f, 0.f};
    float zmx = -1e30f, zmy = -1e30f;
    float m0 = -1e30f, m1 = -1e30f, m2 = -1e30f, m3 = -1e30f;
    for (int i = o0; i < o1; i++) {
        int s = g_srcs[i];
        uint2 xh = g_xh[s * 32 + lane];
        float2 xa = unpackh2(xh.x), xb = unpackh2(xh.y);
        s4.x += xa.x; s4.y += xa.y; s4.z += xb.x; s4.w += xb.y;
        float2 zv = unpackh2(g_zh[s * 32 + lane]);
        zmx = fmaxf(zmx, zv.x); zmy = fmaxf(zmy, zv.y);
        float4 e = el4p[s];
        float e0 = e.x + er4.x, e1 = e.y + er4.y, e2 = e.z + er4.z, e3 = e.w + er4.w;
        e0 = (e0 > 0.f) ? e0 : 0.2f * e0;
        e1 = (e1 > 0.f) ? e1 : 0.2f * e1;
        e2 = (e2 > 0.f) ? e2 : 0.2f * e2;
        e3 = (e3 > 0.f) ? e3 : 0.2f * e3;
        m0 = fmaxf(m0, e0); m1 = fmaxf(m1, e1); m2 = fmaxf(m2, e2); m3 = fmaxf(m3, e3);
    }

    // ---- gate ----
    float inv = (deg > 0) ? 1.0f / (float)deg : 0.0f;
    float4 mean = {s4.x * inv, s4.y * inv, s4.z * inv, s4.w * inv};
    if (deg == 0) { zmx = 0.f; zmy = 0.f; }
    float4 xd = ((const float4*)x)[d * 32 + lane];
    float p[4];
    #pragma unroll
    for (int h = 0; h < 4; h++) {
        int r0 = 4 * lane;
        float v = xd.x * sWg[(r0 + 0) * 4 + h] + xd.y * sWg[(r0 + 1) * 4 + h]
                + xd.z * sWg[(r0 + 2) * 4 + h] + xd.w * sWg[(r0 + 3) * 4 + h];
        int r1 = IN_F + 2 * lane;
        v += zmx * sWg[(r1 + 0) * 4 + h] + zmy * sWg[(r1 + 1) * 4 + h];
        int r2 = IN_F + MAPF + 4 * lane;
        v += mean.x * sWg[(r2 + 0) * 4 + h] + mean.y * sWg[(r2 + 1) * 4 + h]
           + mean.z * sWg[(r2 + 2) * 4 + h] + mean.w * sWg[(r2 + 3) * 4 + h];
        p[h] = v;
    }
    #pragma unroll
    for (int dd = 16; dd >= 1; dd >>= 1) {
        #pragma unroll
        for (int h = 0; h < 4; h++) p[h] += __shfl_xor_sync(0xffffffffu, p[h], dd);
    }
    float gate[4];
    #pragma unroll
    for (int h = 0; h < 4; h++) gate[h] = 1.f / (1.f + __expf(-(p[h] + bg[h])));

    // ---- loop B: softmax-weighted feat accumulate ----
    int h1 = lane >> 4, q = lane & 15;
    float den0 = 0.f, den1 = 0.f, den2 = 0.f, den3 = 0.f;
    float4 acc0 = {0.f, 0.f, 0.f, 0.f}, acc1 = {0.f, 0.f, 0.f, 0.f};
    for (int i = o0; i < o1; i++) {
        int s = g_srcs[i];
        float4 e = el4p[s];
        float e0 = e.x + er4.x, e1 = e.y + er4.y, e2 = e.z + er4.z, e3 = e.w + er4.w;
        e0 = (e0 > 0.f) ? e0 : 0.2f * e0;
        e1 = (e1 > 0.f) ? e1 : 0.2f * e1;
        e2 = (e2 > 0.f) ? e2 : 0.2f * e2;
        e3 = (e3 > 0.f) ? e3 : 0.2f * e3;
        float w0 = __expf(e0 - m0), w1 = __expf(e1 - m1);
        float w2 = __expf(e2 - m2), w3 = __expf(e3 - m3);
        den0 += w0; den1 += w1; den2 += w2; den3 += w3;
        uint2 ua = g_fh[s * 64 + lane];
        uint2 ub = g_fh[s * 64 + 32 + lane];
        float2 fa0 = unpackh2(ua.x), fa1 = unpackh2(ua.y);
        float2 fb0 = unpackh2(ub.x), fb1 = unpackh2(ub.y);
        float wa = (h1 == 0) ? w0 : w1;
        float wb = (h1 == 0) ? w2 : w3;
        acc0.x += wa * fa0.x; acc0.y += wa * fa0.y; acc0.z += wa * fa1.x; acc0.w += wa * fa1.y;
        acc1.x += wb * fb0.x; acc1.y += wb * fb0.y; acc1.z += wb * fb1.x; acc1.w += wb * fb1.y;
    }

    float4 bga = ((const float4*)bgat)[h1 * 16 + q];
    float4 bgb = ((const float4*)bgat)[(h1 + 2) * 16 + q];
    float4 a0, a1;
    if (deg > 0) {
        float ia = 1.f / ((h1 == 0) ? den0 : den1);
        float ib = 1.f / ((h1 == 0) ? den2 : den3);
        a0.x = acc0.x * ia + bga.x; a0.y = acc0.y * ia + bga.y;
        a0.z = acc0.z * ia + bga.z; a0.w = acc0.w * ia + bga.w;
        a1.x = acc1.x * ib + bgb.x; a1.y = acc1.y * ib + bgb.y;
        a1.z = acc1.z * ib + bgb.z; a1.w = acc1.w * ib + bgb.w;
    } else {
        a0 = bga; a1 = bgb;
    }
    float g0 = (h1 == 0) ? gate[0] : gate[1];
    float g1 = (h1 == 0) ? gate[2] : gate[3];
    float4 pp;
    pp.x = g0 * a0.x + g1 * a1.x;
    pp.y = g0 * a0.y + g1 * a1.y;
    pp.z = g0 * a0.z + g1 * a1.z;
    pp.w = g0 * a0.w + g1 * a1.w;
    pp.x += __shfl_xor_sync(0xffffffffu, pp.x, 16);
    pp.y += __shfl_xor_sync(0xffffffffu, pp.y, 16);
    pp.z += __shfl_xor_sync(0xffffffffu, pp.z, 16);
    pp.w += __shfl_xor_sync(0xffffffffu, pp.w, 16);
    pp.x *= 0.25f; pp.y *= 0.25f; pp.z *= 0.25f; pp.w *= 0.25f;
    if (lane < 16) ((float4*)g_gated)[d * 16 + lane] = pp;
}

// ---------------- merge GEMM (tf32): out = [x | gated] @ W_merge + b_merge ------------
__global__ void k_merge(const float* __restrict__ x, const float* __restrict__ Wm,
                        const float* __restrict__ bm, float* __restrict__ out) {
    __shared__ unsigned As[128][20];
    __shared__ unsigned Bs[16][72];
    int t = threadIdx.x;
    int rowBase = blockIdx.x * 128;
    int lane = t & 31, wrp = t >> 5;
    int wm = wrp & 3, wn = wrp >> 2;
    int g = lane >> 2, tig = lane & 3;

    float acc[2][4][4];
    #pragma unroll
    for (int mi = 0; mi < 2; mi++)
        #pragma unroll
        for (int ni = 0; ni < 4; ni++)
            #pragma unroll
            for (int q = 0; q < 4; q++) acc[mi][ni][q] = 0.f;

    int ar0 = t >> 2, akq = t & 3;
    int ar1 = ar0 + 64;
    int gr0 = rowBase + ar0; if (gr0 >= NN) gr0 = NN - 1;
    int gr1 = rowBase + ar1; if (gr1 >= NN) gr1 = NN - 1;
    int bk = t >> 4, bq = t & 15;

    for (int kt = 0; kt < 12; kt++) {
        int k0 = kt * 16 + akq * 4;
        float4 a0v, a1v;
        if (k0 < IN_F) {
            a0v = *(const float4*)&x[gr0 * IN_F + k0];
            a1v = *(const float4*)&x[gr1 * IN_F + k0];
        } else {
            a0v = *(const float4*)&g_gated[gr0 * OUT_F + (k0 - IN_F)];
            a1v = *(const float4*)&g_gated[gr1 * OUT_F + (k0 - IN_F)];
        }
        float4 bv = *(const float4*)&Wm[(kt * 16 + bk) * 64 + bq * 4];
        uint4 u0 = {f2tf(a0v.x), f2tf(a0v.y), f2tf(a0v.z), f2tf(a0v.w)};
        uint4 u1 = {f2tf(a1v.x), f2tf(a1v.y), f2tf(a1v.z), f2tf(a1v.w)};
        uint4 ub = {f2tf(bv.x),  f2tf(bv.y),  f2tf(bv.z),  f2tf(bv.w)};
        *(uint4*)&As[ar0][akq * 4] = u0;
        *(uint4*)&As[ar1][akq * 4] = u1;
        *(uint4*)&Bs[bk][bq * 4]   = ub;
        __syncthreads();
        #pragma unroll
        for (int ki = 0; ki < 2; ki++) {
            unsigned a[2][4];
            #pragma unroll
            for (int mi = 0; mi < 2; mi++) {
                int rm = wm * 32 + mi * 16;
                a[mi][0] = As[rm + g][ki * 8 + tig];
                a[mi][1] = As[rm + g + 8][ki * 8 + tig];
                a[mi][2] = As[rm + g][ki * 8 + tig + 4];
                a[mi][3] = As[rm + g + 8][ki * 8 + tig + 4];
            }
            #pragma unroll
            for (int ni = 0; ni < 4; ni++) {
                int cn = wn * 32 + ni * 8;
                unsigned b0 = Bs[ki * 8 + tig][cn + g];
                unsigned b1 = Bs[ki * 8 + tig + 4][cn + g];
                mma8(acc[0][ni], a[0][0], a[0][1], a[0][2], a[0][3], b0, b1);
                mma8(acc[1][ni], a[1][0], a[1][1], a[1][2], a[1][3], b0, b1);
            }
        }
        __syncthreads();
    }

    #pragma unroll
    for (int mi = 0; mi < 2; mi++) {
        #pragma unroll
        for (int ni = 0; ni < 4; ni++) {
            int lc = wn * 32 + ni * 8 + tig * 2;
            #pragma unroll
            for (int half = 0; half < 2; half++) {
                int r = rowBase + wm * 32 + mi * 16 + g + half * 8;
                if (r < NN) {
                    out[r * OUT_F + lc]     = acc[mi][ni][half * 2 + 0] + bm[lc];
                    out[r * OUT_F + lc + 1] = acc[mi][ni][half * 2 + 1] + bm[lc + 1];
                }
            }
        }
    }
}

// ---------------- launch ----------------
extern "C" void kernel_launch(void* const* d_in, const int* in_sizes, int n_in,
                              void* d_out, int out_size) {
    const float* x      = (const float*)d_in[0];
    const int*   ei     = (const int*)d_in[1];
    const float* W_gm   = (const float*)d_in[2];
    const float* b_gm   = (const float*)d_in[3];
    const float* W_gate = (const float*)d_in[4];
    const float* b_gate = (const float*)d_in[5];
    const float* W_fc   = (const float*)d_in[6];
    const float* attn_l = (const float*)d_in[7];
    const float* attn_r = (const float*)d_in[8];
    const float* b_gat  = (const float*)d_in[9];
    const float* W_mrg  = (const float*)d_in[10];
    const float* b_mrg  = (const float*)d_in[11];
    float* out = (float*)d_out;

    const int* src = ei;
    const int* dst = ei + EE;

    k_zero<<<(NN + 255) / 256, 256>>>();
    k_hist<<<(EE + 255) / 256, 256>>>(dst);
    k_scan<<<1, 1024>>>();
    k_scatter<<<(EE + 255) / 256, 256>>>(src, dst);
    k_xhalf<<<(NN * 32 + 255) / 256, 256>>>(x);
    k_gemm1<<<dim3((NN + 127) / 128, 5), 256>>>(x, W_gm, b_gm, W_fc);
    k_elr<<<(NN + 7) / 8, 256>>>(attn_l, attn_r);
    k_agg<<<(NN + 7) / 8, 256>>>(x, W_gate, b_gate, b_gat);
    k_merge<<<(NN + 127) / 128, 256>>>(x, W_mrg, b_mrg, out);
}

// round 4
// speedup vs baseline: 1.5287x; 1.1409x over previous
#include <cuda_runtime.h>
#include <cuda_fp16.h>

#define NN   50000
#define EE   800000
#define IN_F 128
#define OUT_F 64
#define MAPF 64
#define NH   4

// ---------------- scratch (static device globals; no allocation) ----------------
__device__ int   g_count[NN];
__device__ int   g_off[NN + 1];
__device__ int   g_cursor[NN];
__device__ int   g_srcs[EE];
__device__ uint2    g_xh[NN * 32];   // x  as fp16: 128 halfs/row
__device__ unsigned g_zh[NN * 32];   // z  as fp16: 64 halfs/row
__device__ uint2    g_fh[NN * 64];   // feat as fp16: 256 halfs/row ([h][64])
__device__ float g_el[NN * NH];
__device__ float g_er[NN * NH];
__device__ float g_gated[NN * OUT_F];

// ---------------- helpers ----------------
__device__ __forceinline__ unsigned f2tf(float f) {
    unsigned u;
    asm("cvt.rna.tf32.f32 %0, %1;" : "=r"(u) : "f"(f));
    return u;
}
__device__ __forceinline__ void mma8(float* c, unsigned a0, unsigned a1, unsigned a2,
                                     unsigned a3, unsigned b0, unsigned b1) {
    asm volatile(
        "mma.sync.aligned.m16n8k8.row.col.f32.tf32.tf32.f32 "
        "{%0,%1,%2,%3},{%4,%5,%6,%7},{%8,%9},{%0,%1,%2,%3};"
        : "+f"(c[0]), "+f"(c[1]), "+f"(c[2]), "+f"(c[3])
        : "r"(a0), "r"(a1), "r"(a2), "r"(a3), "r"(b0), "r"(b1));
}
__device__ __forceinline__ unsigned packh2(float a, float b) {
    __half2 h = __floats2half2_rn(a, b);
    return *(unsigned*)&h;
}
__device__ __forceinline__ float2 unpackh2(unsigned u) {
    return __half22float2(*(__half2*)&u);
}

// ---------------- CSR build ----------------
__global__ void k_zero() {
    int i = blockIdx.x * blockDim.x + threadIdx.x;
    if (i < NN) g_count[i] = 0;
}

__global__ void k_hist(const int* __restrict__ dst) {
    int e = blockIdx.x * blockDim.x + threadIdx.x;
    if (e < EE) atomicAdd(&g_count[dst[e]], 1);
}

__global__ void k_scan() {
    __shared__ int warp_sums[32];
    __shared__ int s_base;
    int t = threadIdx.x, lane = t & 31, wid = t >> 5;
    if (t == 0) s_base = 0;
    __syncthreads();
    for (int base = 0; base < NN; base += 1024) {
        int i = base + t;
        int v = (i < NN) ? g_count[i] : 0;
        int xs = v;
        #pragma unroll
        for (int d = 1; d < 32; d <<= 1) {
            int y = __shfl_up_sync(0xffffffffu, xs, d);
            if (lane >= d) xs += y;
        }
        if (lane == 31) warp_sums[wid] = xs;
        __syncthreads();
        if (wid == 0) {
            int s = warp_sums[lane];
            #pragma unroll
            for (int d = 1; d < 32; d <<= 1) {
                int y = __shfl_up_sync(0xffffffffu, s, d);
                if (lane >= d) s += y;
            }
            warp_sums[lane] = s;
        }
        __syncthreads();
        int warp_off = (wid > 0) ? warp_sums[wid - 1] : 0;
        int excl = s_base + warp_off + xs - v;
        if (i < NN) { g_off[i] = excl; g_cursor[i] = excl; }
        __syncthreads();
        if (t == 1023) s_base = excl + v;
    }
    __syncthreads();
    if (t == 0) g_off[NN] = s_base;
}

__global__ void k_scatter(const int* __restrict__ src, const int* __restrict__ dst) {
    int e = blockIdx.x * blockDim.x + threadIdx.x;
    if (e < EE) {
        int d = dst[e];
        int p = atomicAdd(&g_cursor[d], 1);
        g_srcs[p] = src[e];
    }
}

// ---------------- x -> fp16 copy ----------------
__global__ void k_xhalf(const float* __restrict__ x) {
    int i = blockIdx.x * blockDim.x + threadIdx.x;
    if (i < NN * 32) {
        float4 v = ((const float4*)x)[i];
        uint2 u;
        u.x = packh2(v.x, v.y);
        u.y = packh2(v.z, v.w);
        g_xh[i] = u;
    }
}

// ---------------- GEMM1 (tf32): z_h (nt=0), feat_h (nt=1..4) ----------------
__global__ void k_gemm1(const float* __restrict__ x,
                        const float* __restrict__ Wgm, const float* __restrict__ bgm,
                        const float* __restrict__ Wfc) {
    __shared__ unsigned As[128][20];
    __shared__ unsigned Bs[16][72];
    int t = threadIdx.x;
    int nt = blockIdx.y;
    int rowBase = blockIdx.x * 128;
    const float* W; int ldw, colBase;
    if (nt == 0) { W = Wgm; ldw = 64;  colBase = 0; }
    else         { W = Wfc; ldw = 256; colBase = (nt - 1) * 64; }

    int lane = t & 31, wrp = t >> 5;
    int wm = wrp & 3, wn = wrp >> 2;
    int g = lane >> 2, tig = lane & 3;

    float acc[2][4][4];
    #pragma unroll
    for (int mi = 0; mi < 2; mi++)
        #pragma unroll
        for (int ni = 0; ni < 4; ni++)
            #pragma unroll
            for (int q = 0; q < 4; q++) acc[mi][ni][q] = 0.f;

    int ar0 = t >> 2, akq = t & 3;
    int ar1 = ar0 + 64;
    int gr0 = rowBase + ar0; if (gr0 >= NN) gr0 = NN - 1;
    int gr1 = rowBase + ar1; if (gr1 >= NN) gr1 = NN - 1;
    int bk = t >> 4, bq = t & 15;

    for (int kt = 0; kt < 8; kt++) {
        float4 a0v = *(const float4*)&x[gr0 * IN_F + kt * 16 + akq * 4];
        float4 a1v = *(const float4*)&x[gr1 * IN_F + kt * 16 + akq * 4];
        float4 bv  = *(const float4*)&W[(kt * 16 + bk) * ldw + colBase + bq * 4];
        uint4 u0 = {f2tf(a0v.x), f2tf(a0v.y), f2tf(a0v.z), f2tf(a0v.w)};
        uint4 u1 = {f2tf(a1v.x), f2tf(a1v.y), f2tf(a1v.z), f2tf(a1v.w)};
        uint4 ub = {f2tf(bv.x),  f2tf(bv.y),  f2tf(bv.z),  f2tf(bv.w)};
        *(uint4*)&As[ar0][akq * 4] = u0;
        *(uint4*)&As[ar1][akq * 4] = u1;
        *(uint4*)&Bs[bk][bq * 4]   = ub;
        __syncthreads();
        #pragma unroll
        for (int ki = 0; ki < 2; ki++) {
            unsigned a[2][4];
            #pragma unroll
            for (int mi = 0; mi < 2; mi++) {
                int rm = wm * 32 + mi * 16;
                a[mi][0] = As[rm + g][ki * 8 + tig];
                a[mi][1] = As[rm + g + 8][ki * 8 + tig];
                a[mi][2] = As[rm + g][ki * 8 + tig + 4];
                a[mi][3] = As[rm + g + 8][ki * 8 + tig + 4];
            }
            #pragma unroll
            for (int ni = 0; ni < 4; ni++) {
                int cn = wn * 32 + ni * 8;
                unsigned b0 = Bs[ki * 8 + tig][cn + g];
                unsigned b1 = Bs[ki * 8 + tig + 4][cn + g];
                mma8(acc[0][ni], a[0][0], a[0][1], a[0][2], a[0][3], b0, b1);
                mma8(acc[1][ni], a[1][0], a[1][1], a[1][2], a[1][3], b0, b1);
            }
        }
        __syncthreads();
    }

    #pragma unroll
    for (int mi = 0; mi < 2; mi++) {
        #pragma unroll
        for (int ni = 0; ni < 4; ni++) {
            int lc = wn * 32 + ni * 8 + tig * 2;
            #pragma unroll
            for (int half = 0; half < 2; half++) {
                int r = rowBase + wm * 32 + mi * 16 + g + half * 8;
                if (r < NN) {
                    float v0 = acc[mi][ni][half * 2 + 0];
                    float v1 = acc[mi][ni][half * 2 + 1];
                    if (nt == 0) {
                        g_zh[r * 32 + (lc >> 1)] = packh2(v0 + bgm[lc], v1 + bgm[lc + 1]);
                    } else {
                        ((unsigned*)g_fh)[r * 128 + ((colBase + lc) >> 1)] = packh2(v0, v1);
                    }
                }
            }
        }
    }
}

// ---------------- el/er: per-node head dot products (fp16 feat) ----------------
__global__ void k_elr(const float* __restrict__ al, const float* __restrict__ ar) {
    int w = threadIdx.x >> 5, lane = threadIdx.x & 31;
    int nodeid = blockIdx.x * 8 + w;
    if (nodeid >= NN) return;
    int h1 = lane >> 4, q = lane & 15;
    uint2 ua = g_fh[nodeid * 64 + lane];
    uint2 ub = g_fh[nodeid * 64 + 32 + lane];
    float2 fa0 = unpackh2(ua.x), fa1 = unpackh2(ua.y);
    float2 fb0 = unpackh2(ub.x), fb1 = unpackh2(ub.y);
    const float4* al4 = (const float4*)al;
    const float4* ar4 = (const float4*)ar;
    float4 a0 = al4[h1 * 16 + q], a1 = al4[(h1 + 2) * 16 + q];
    float4 r0 = ar4[h1 * 16 + q], r1 = ar4[(h1 + 2) * 16 + q];
    float el0 = fa0.x * a0.x + fa0.y * a0.y + fa1.x * a0.z + fa1.y * a0.w;
    float el1 = fb0.x * a1.x + fb0.y * a1.y + fb1.x * a1.z + fb1.y * a1.w;
    float er0 = fa0.x * r0.x + fa0.y * r0.y + fa1.x * r0.z + fa1.y * r0.w;
    float er1 = fb0.x * r1.x + fb0.y * r1.y + fb1.x * r1.z + fb1.y * r1.w;
    #pragma unroll
    for (int d = 8; d >= 1; d >>= 1) {
        el0 += __shfl_down_sync(0xffffffffu, el0, d);
        el1 += __shfl_down_sync(0xffffffffu, el1, d);
        er0 += __shfl_down_sync(0xffffffffu, er0, d);
        er1 += __shfl_down_sync(0xffffffffu, er1, d);
    }
    if ((lane & 15) == 0) {
        g_el[nodeid * 4 + h1]     = el0;
        g_el[nodeid * 4 + h1 + 2] = el1;
        g_er[nodeid * 4 + h1]     = er0;
        g_er[nodeid * 4 + h1 + 2] = er1;
    }
}

// ---------------- fused single-pass agg -------------------------------------------
// exp(e) without max-shift: alpha = exp(e)/sum(exp(e)) is exactly the reference
// softmax (shift invariance); |e| is O(1) here so no overflow risk.
__global__ void k_agg(const float* __restrict__ x,
                      const float* __restrict__ Wg, const float* __restrict__ bg,
                      const float* __restrict__ bgat) {
    __shared__ float sWg[(2 * IN_F + MAPF) * NH];
    for (int i = threadIdx.x; i < (2 * IN_F + MAPF) * NH; i += blockDim.x) sWg[i] = Wg[i];
    __syncthreads();
    int w = threadIdx.x >> 5, lane = threadIdx.x & 31;
    int d = blockIdx.x * 8 + w;
    if (d >= NN) return;
    int o0 = g_off[d], o1 = g_off[d + 1];
    int deg = o1 - o0;

    const float4* el4p = (const float4*)g_el;
    float4 er4 = ((const float4*)g_er)[d];
    int h1 = lane >> 4, q = lane & 15;

    float4 s4 = {0.f, 0.f, 0.f, 0.f};
    float zmx = -1e30f, zmy = -1e30f;
    float den0 = 0.f, den1 = 0.f, den2 = 0.f, den3 = 0.f;
    float4 acc0 = {0.f, 0.f, 0.f, 0.f}, acc1 = {0.f, 0.f, 0.f, 0.f};

    int i = o0;
    for (; i + 1 < o1; i += 2) {
        int s0 = g_srcs[i];
        int s1 = g_srcs[i + 1];
        // issue all gathers for both edges up front (independent loads)
        uint2 xh0 = g_xh[s0 * 32 + lane];
        uint2 xh1 = g_xh[s1 * 32 + lane];
        unsigned zu0 = g_zh[s0 * 32 + lane];
        unsigned zu1 = g_zh[s1 * 32 + lane];
        float4 ev0 = el4p[s0];
        float4 ev1 = el4p[s1];
        uint2 ua0 = g_fh[s0 * 64 + lane];
        uint2 ub0 = g_fh[s0 * 64 + 32 + lane];
        uint2 ua1 = g_fh[s1 * 64 + lane];
        uint2 ub1 = g_fh[s1 * 64 + 32 + lane];

        // edge 0
        {
            float2 xa = unpackh2(xh0.x), xb = unpackh2(xh0.y);
            s4.x += xa.x; s4.y += xa.y; s4.z += xb.x; s4.w += xb.y;
            float2 zv = unpackh2(zu0);
            zmx = fmaxf(zmx, zv.x); zmy = fmaxf(zmy, zv.y);
            float e0 = ev0.x + er4.x, e1 = ev0.y + er4.y;
            float e2 = ev0.z + er4.z, e3 = ev0.w + er4.w;
            e0 = (e0 > 0.f) ? e0 : 0.2f * e0;
            e1 = (e1 > 0.f) ? e1 : 0.2f * e1;
            e2 = (e2 > 0.f) ? e2 : 0.2f * e2;
            e3 = (e3 > 0.f) ? e3 : 0.2f * e3;
            float w0 = __expf(e0), w1 = __expf(e1);
            float w2 = __expf(e2), w3 = __expf(e3);
            den0 += w0; den1 += w1; den2 += w2; den3 += w3;
            float2 fa0 = unpackh2(ua0.x), fa1 = unpackh2(ua0.y);
            float2 fb0 = unpackh2(ub0.x), fb1 = unpackh2(ub0.y);
            float wa = (h1 == 0) ? w0 : w1;
            float wb = (h1 == 0) ? w2 : w3;
            acc0.x += wa * fa0.x; acc0.y += wa * fa0.y; acc0.z += wa * fa1.x; acc0.w += wa * fa1.y;
            acc1.x += wb * fb0.x; acc1.y += wb * fb0.y; acc1.z += wb * fb1.x; acc1.w += wb * fb1.y;
        }
        // edge 1
        {
            float2 xa = unpackh2(xh1.x), xb = unpackh2(xh1.y);
            s4.x += xa.x; s4.y += xa.y; s4.z += xb.x; s4.w += xb.y;
            float2 zv = unpackh2(zu1);
            zmx = fmaxf(zmx, zv.x); zmy = fmaxf(zmy, zv.y);
            float e0 = ev1.x + er4.x, e1 = ev1.y + er4.y;
            float e2 = ev1.z + er4.z, e3 = ev1.w + er4.w;
            e0 = (e0 > 0.f) ? e0 : 0.2f * e0;
            e1 = (e1 > 0.f) ? e1 : 0.2f * e1;
            e2 = (e2 > 0.f) ? e2 : 0.2f * e2;
            e3 = (e3 > 0.f) ? e3 : 0.2f * e3;
            float w0 = __expf(e0), w1 = __expf(e1);
            float w2 = __expf(e2), w3 = __expf(e3);
            den0 += w0; den1 += w1; den2 += w2; den3 += w3;
            float2 fa0 = unpackh2(ua1.x), fa1 = unpackh2(ua1.y);
            float2 fb0 = unpackh2(ub1.x), fb1 = unpackh2(ub1.y);
            float wa = (h1 == 0) ? w0 : w1;
            float wb = (h1 == 0) ? w2 : w3;
            acc0.x += wa * fa0.x; acc0.y += wa * fa0.y; acc0.z += wa * fa1.x; acc0.w += wa * fa1.y;
            acc1.x += wb * fb0.x; acc1.y += wb * fb0.y; acc1.z += wb * fb1.x; acc1.w += wb * fb1.y;
        }
    }
    if (i < o1) {
        int s0 = g_srcs[i];
        uint2 xh0 = g_xh[s0 * 32 + lane];
        unsigned zu0 = g_zh[s0 * 32 + lane];
        float4 ev0 = el4p[s0];
        uint2 ua0 = g_fh[s0 * 64 + lane];
        uint2 ub0 = g_fh[s0 * 64 + 32 + lane];
        float2 xa = unpackh2(xh0.x), xb = unpackh2(xh0.y);
        s4.x += xa.x; s4.y += xa.y; s4.z += xb.x; s4.w += xb.y;
        float2 zv = unpackh2(zu0);
        zmx = fmaxf(zmx, zv.x); zmy = fmaxf(zmy, zv.y);
        float e0 = ev0.x + er4.x, e1 = ev0.y + er4.y;
        float e2 = ev0.z + er4.z, e3 = ev0.w + er4.w;
        e0 = (e0 > 0.f) ? e0 : 0.2f * e0;
        e1 = (e1 > 0.f) ? e1 : 0.2f * e1;
        e2 = (e2 > 0.f) ? e2 : 0.2f * e2;
        e3 = (e3 > 0.f) ? e3 : 0.2f * e3;
        float w0 = __expf(e0), w1 = __expf(e1);
        float w2 = __expf(e2), w3 = __expf(e3);
        den0 += w0; den1 += w1; den2 += w2; den3 += w3;
        float2 fa0 = unpackh2(ua0.x), fa1 = unpackh2(ua0.y);
        float2 fb0 = unpackh2(ub0.x), fb1 = unpackh2(ub0.y);
        float wa = (h1 == 0) ? w0 : w1;
        float wb = (h1 == 0) ? w2 : w3;
        acc0.x += wa * fa0.x; acc0.y += wa * fa0.y; acc0.z += wa * fa1.x; acc0.w += wa * fa1.y;
        acc1.x += wb * fb0.x; acc1.y += wb * fb0.y; acc1.z += wb * fb1.x; acc1.w += wb * fb1.y;
    }

    // ---- gate from mean/max ----
    float inv = (deg > 0) ? 1.0f / (float)deg : 0.0f;
    float4 mean = {s4.x * inv, s4.y * inv, s4.z * inv, s4.w * inv};
    if (deg == 0) { zmx = 0.f; zmy = 0.f; }
    float4 xd = ((const float4*)x)[d * 32 + lane];
    float p[4];
    #pragma unroll
    for (int h = 0; h < 4; h++) {
        int r0 = 4 * lane;
        float v = xd.x * sWg[(r0 + 0) * 4 + h] + xd.y * sWg[(r0 + 1) * 4 + h]
                + xd.z * sWg[(r0 + 2) * 4 + h] + xd.w * sWg[(r0 + 3) * 4 + h];
        int r1 = IN_F + 2 * lane;
        v += zmx * sWg[(r1 + 0) * 4 + h] + zmy * sWg[(r1 + 1) * 4 + h];
        int r2 = IN_F + MAPF + 4 * lane;
        v += mean.x * sWg[(r2 + 0) * 4 + h] + mean.y * sWg[(r2 + 1) * 4 + h]
           + mean.z * sWg[(r2 + 2) * 4 + h] + mean.w * sWg[(r2 + 3) * 4 + h];
        p[h] = v;
    }
    #pragma unroll
    for (int dd = 16; dd >= 1; dd >>= 1) {
        #pragma unroll
        for (int h = 0; h < 4; h++) p[h] += __shfl_xor_sync(0xffffffffu, p[h], dd);
    }
    float gate[4];
    #pragma unroll
    for (int h = 0; h < 4; h++) gate[h] = 1.f / (1.f + __expf(-(p[h] + bg[h])));

    // ---- normalize, bias, gate, head-average, store ----
    float4 bga = ((const float4*)bgat)[h1 * 16 + q];
    float4 bgb = ((const float4*)bgat)[(h1 + 2) * 16 + q];
    float4 a0, a1;
    if (deg > 0) {
        float ia = 1.f / ((h1 == 0) ? den0 : den1);
        float ib = 1.f / ((h1 == 0) ? den2 : den3);
        a0.x = acc0.x * ia + bga.x; a0.y = acc0.y * ia + bga.y;
        a0.z = acc0.z * ia + bga.z; a0.w = acc0.w * ia + bga.w;
        a1.x = acc1.x * ib + bgb.x; a1.y = acc1.y * ib + bgb.y;
        a1.z = acc1.z * ib + bgb.z; a1.w = acc1.w * ib + bgb.w;
    } else {
        a0 = bga; a1 = bgb;
    }
    float g0 = (h1 == 0) ? gate[0] : gate[1];
    float g1 = (h1 == 0) ? gate[2] : gate[3];
    float4 pp;
    pp.x = g0 * a0.x + g1 * a1.x;
    pp.y = g0 * a0.y + g1 * a1.y;
    pp.z = g0 * a0.z + g1 * a1.z;
    pp.w = g0 * a0.w + g1 * a1.w;
    pp.x += __shfl_xor_sync(0xffffffffu, pp.x, 16);
    pp.y += __shfl_xor_sync(0xffffffffu, pp.y, 16);
    pp.z += __shfl_xor_sync(0xffffffffu, pp.z, 16);
    pp.w += __shfl_xor_sync(0xffffffffu, pp.w, 16);
    pp.x *= 0.25f; pp.y *= 0.25f; pp.z *= 0.25f; pp.w *= 0.25f;
    if (lane < 16) ((float4*)g_gated)[d * 16 + lane] = pp;
}

// ---------------- merge GEMM (tf32): out = [x | gated] @ W_merge + b_merge ------------
__global__ void k_merge(const float* __restrict__ x, const float* __restrict__ Wm,
                        const float* __restrict__ bm, float* __restrict__ out) {
    __shared__ unsigned As[128][20];
    __shared__ unsigned Bs[16][72];
    int t = threadIdx.x;
    int rowBase = blockIdx.x * 128;
    int lane = t & 31, wrp = t >> 5;
    int wm = wrp & 3, wn = wrp >> 2;
    int g = lane >> 2, tig = lane & 3;

    float acc[2][4][4];
    #pragma unroll
    for (int mi = 0; mi < 2; mi++)
        #pragma unroll
        for (int ni = 0; ni < 4; ni++)
            #pragma unroll
            for (int q = 0; q < 4; q++) acc[mi][ni][q] = 0.f;

    int ar0 = t >> 2, akq = t & 3;
    int ar1 = ar0 + 64;
    int gr0 = rowBase + ar0; if (gr0 >= NN) gr0 = NN - 1;
    int gr1 = rowBase + ar1; if (gr1 >= NN) gr1 = NN - 1;
    int bk = t >> 4, bq = t & 15;

    for (int kt = 0; kt < 12; kt++) {
        int k0 = kt * 16 + akq * 4;
        float4 a0v, a1v;
        if (k0 < IN_F) {
            a0v = *(const float4*)&x[gr0 * IN_F + k0];
            a1v = *(const float4*)&x[gr1 * IN_F + k0];
        } else {
            a0v = *(const float4*)&g_gated[gr0 * OUT_F + (k0 - IN_F)];
            a1v = *(const float4*)&g_gated[gr1 * OUT_F + (k0 - IN_F)];
        }
        float4 bv = *(const float4*)&Wm[(kt * 16 + bk) * 64 + bq * 4];
        uint4 u0 = {f2tf(a0v.x), f2tf(a0v.y), f2tf(a0v.z), f2tf(a0v.w)};
        uint4 u1 = {f2tf(a1v.x), f2tf(a1v.y), f2tf(a1v.z), f2tf(a1v.w)};
        uint4 ub = {f2tf(bv.x),  f2tf(bv.y),  f2tf(bv.z),  f2tf(bv.w)};
        *(uint4*)&As[ar0][akq * 4] = u0;
        *(uint4*)&As[ar1][akq * 4] = u1;
        *(uint4*)&Bs[bk][bq * 4]   = ub;
        __syncthreads();
        #pragma unroll
        for (int ki = 0; ki < 2; ki++) {
            unsigned a[2][4];
            #pragma unroll
            for (int mi = 0; mi < 2; mi++) {
                int rm = wm * 32 + mi * 16;
                a[mi][0] = As[rm + g][ki * 8 + tig];
                a[mi][1] = As[rm + g + 8][ki * 8 + tig];
                a[mi][2] = As[rm + g][ki * 8 + tig + 4];
                a[mi][3] = As[rm + g + 8][ki * 8 + tig + 4];
            }
            #pragma unroll
            for (int ni = 0; ni < 4; ni++) {
                int cn = wn * 32 + ni * 8;
                unsigned b0 = Bs[ki * 8 + tig][cn + g];
                unsigned b1 = Bs[ki * 8 + tig + 4][cn + g];
                mma8(acc[0][ni], a[0][0], a[0][1], a[0][2], a[0][3], b0, b1);
                mma8(acc[1][ni], a[1][0], a[1][1], a[1][2], a[1][3], b0, b1);
            }
        }
        __syncthreads();
    }

    #pragma unroll
    for (int mi = 0; mi < 2; mi++) {
        #pragma unroll
        for (int ni = 0; ni < 4; ni++) {
            int lc = wn * 32 + ni * 8 + tig * 2;
            #pragma unroll
            for (int half = 0; half < 2; half++) {
                int r = rowBase + wm * 32 + mi * 16 + g + half * 8;
                if (r < NN) {
                    out[r * OUT_F + lc]     = acc[mi][ni][half * 2 + 0] + bm[lc];
                    out[r * OUT_F + lc + 1] = acc[mi][ni][half * 2 + 1] + bm[lc + 1];
                }
            }
        }
    }
}

// ---------------- launch ----------------
extern "C" void kernel_launch(void* const* d_in, const int* in_sizes, int n_in,
                              void* d_out, int out_size) {
    const float* x      = (const float*)d_in[0];
    const int*   ei     = (const int*)d_in[1];
    const float* W_gm   = (const float*)d_in[2];
    const float* b_gm   = (const float*)d_in[3];
    const float* W_gate = (const float*)d_in[4];
    const float* b_gate = (const float*)d_in[5];
    const float* W_fc   = (const float*)d_in[6];
    const float* attn_l = (const float*)d_in[7];
    const float* attn_r = (const float*)d_in[8];
    const float* b_gat  = (const float*)d_in[9];
    const float* W_mrg  = (const float*)d_in[10];
    const float* b_mrg  = (const float*)d_in[11];
    float* out = (float*)d_out;

    const int* src = ei;
    const int* dst = ei + EE;

    k_zero<<<(NN + 255) / 256, 256>>>();
    k_hist<<<(EE + 255) / 256, 256>>>(dst);
    k_scan<<<1, 1024>>>();
    k_scatter<<<(EE + 255) / 256, 256>>>(src, dst);
    k_xhalf<<<(NN * 32 + 255) / 256, 256>>>(x);
    k_gemm1<<<dim3((NN + 127) / 128, 5), 256>>>(x, W_gm, b_gm, W_fc);
    k_elr<<<(NN + 7) / 8, 256>>>(attn_l, attn_r);
    k_agg<<<(NN + 7) / 8, 256>>>(x, W_gate, b_gate, b_gat);
    k_merge<<<(NN + 127) / 128, 256>>>(x, W_mrg, b_mrg, out);
}

// round 5
// speedup vs baseline: 1.6269x; 1.0642x over previous
#include <cuda_runtime.h>
#include <cuda_fp16.h>

#define NN   50000
#define EE   800000
#define IN_F 128
#define OUT_F 64
#define MAPF 64
#define NH   4
#define SCAN_BS 512
#define NB ((NN + SCAN_BS - 1) / SCAN_BS)   // 98

// ---------------- scratch (static device globals; no allocation) ----------------
__device__ int   g_count[NN];
__device__ int   g_off[NN + 1];
__device__ int   g_cursor[NN];
__device__ int   g_bsum[NB];
__device__ int   g_bbase[NB];
__device__ int   g_srcs[EE];
__device__ uint2    g_xh[NN * 32];   // x  as fp16: 128 halfs/row
__device__ unsigned g_zh[NN * 32];   // z  as fp16: 64 halfs/row
__device__ uint2    g_fh[NN * 64];   // feat as fp16: 256 halfs/row ([h][64])
__device__ float g_el[NN * NH];
__device__ float g_er[NN * NH];
__device__ float g_gated[NN * OUT_F];

// ---------------- helpers ----------------
__device__ __forceinline__ unsigned f2tf(float f) {
    unsigned u;
    asm("cvt.rna.tf32.f32 %0, %1;" : "=r"(u) : "f"(f));
    return u;
}
__device__ __forceinline__ void mma8(float* c, unsigned a0, unsigned a1, unsigned a2,
                                     unsigned a3, unsigned b0, unsigned b1) {
    asm volatile(
        "mma.sync.aligned.m16n8k8.row.col.f32.tf32.tf32.f32 "
        "{%0,%1,%2,%3},{%4,%5,%6,%7},{%8,%9},{%0,%1,%2,%3};"
        : "+f"(c[0]), "+f"(c[1]), "+f"(c[2]), "+f"(c[3])
        : "r"(a0), "r"(a1), "r"(a2), "r"(a3), "r"(b0), "r"(b1));
}
__device__ __forceinline__ unsigned packh2(float a, float b) {
    __half2 h = __floats2half2_rn(a, b);
    return *(unsigned*)&h;
}
__device__ __forceinline__ float2 unpackh2(unsigned u) {
    return __half22float2(*(__half2*)&u);
}

// ---------------- CSR build ----------------
__global__ void k_zero() {
    int i = blockIdx.x * blockDim.x + threadIdx.x;
    if (i < NN) g_count[i] = 0;
}

__global__ void k_hist(const int* __restrict__ dst) {
    int e4 = blockIdx.x * blockDim.x + threadIdx.x;
    if (e4 < EE / 4) {
        int4 d = ((const int4*)dst)[e4];
        atomicAdd(&g_count[d.x], 1);
        atomicAdd(&g_count[d.y], 1);
        atomicAdd(&g_count[d.z], 1);
        atomicAdd(&g_count[d.w], 1);
    }
}

// scan stage 1: per-block exclusive scan (in-block) + block totals
__global__ void k_scan1() {
    __shared__ int wsum[16];
    int b = blockIdx.x, t = threadIdx.x, lane = t & 31, w = t >> 5;
    int i = b * SCAN_BS + t;
    int v = (i < NN) ? g_count[i] : 0;
    int xs = v;
    #pragma unroll
    for (int d = 1; d < 32; d <<= 1) {
        int y = __shfl_up_sync(0xffffffffu, xs, d);
        if (lane >= d) xs += y;
    }
    if (lane == 31) wsum[w] = xs;
    __syncthreads();
    if (w == 0) {
        int s = (lane < 16) ? wsum[lane] : 0;
        #pragma unroll
        for (int d = 1; d < 16; d <<= 1) {
            int y = __shfl_up_sync(0xffffffffu, s, d);
            if (lane >= d) s += y;
        }
        if (lane < 16) wsum[lane] = s;
    }
    __syncthreads();
    int base = (w > 0) ? wsum[w - 1] : 0;
    if (i < NN) g_off[i] = base + xs - v;   // in-block exclusive
    if (t == SCAN_BS - 1) g_bsum[b] = wsum[15];
}

// scan stage 2: scan 98 block sums -> exclusive block bases (single block, 128 thr)
__global__ void k_scan2() {
    __shared__ int ws[4];
    int t = threadIdx.x, lane = t & 31, w = t >> 5;
    int v = (t < NB) ? g_bsum[t] : 0;
    int xs = v;
    #pragma unroll
    for (int d = 1; d < 32; d <<= 1) {
        int y = __shfl_up_sync(0xffffffffu, xs, d);
        if (lane >= d) xs += y;
    }
    if (lane == 31) ws[w] = xs;
    __syncthreads();
    if (t == 0) {
        int a = 0;
        #pragma unroll
        for (int k = 0; k < 4; k++) { int tmp = ws[k]; ws[k] = a; a += tmp; }
    }
    __syncthreads();
    if (t < NB) g_bbase[t] = ws[w] + xs - v;
}

// scan stage 3: add block base, init cursor
__global__ void k_scan3() {
    int b = blockIdx.x, t = threadIdx.x;
    int i = b * SCAN_BS + t;
    if (i < NN) {
        int o = g_off[i] + g_bbase[b];
        g_off[i] = o;
        g_cursor[i] = o;
    }
    if (i == 0) g_off[NN] = EE;
}

__global__ void k_scatter(const int* __restrict__ src, const int* __restrict__ dst) {
    int e4 = blockIdx.x * blockDim.x + threadIdx.x;
    if (e4 < EE / 4) {
        int4 d = ((const int4*)dst)[e4];
        int4 s = ((const int4*)src)[e4];
        g_srcs[atomicAdd(&g_cursor[d.x], 1)] = s.x;
        g_srcs[atomicAdd(&g_cursor[d.y], 1)] = s.y;
        g_srcs[atomicAdd(&g_cursor[d.z], 1)] = s.z;
        g_srcs[atomicAdd(&g_cursor[d.w], 1)] = s.w;
    }
}

// ---------------- x -> fp16 copy ----------------
__global__ void k_xhalf(const float* __restrict__ x) {
    int i = blockIdx.x * blockDim.x + threadIdx.x;
    if (i < NN * 32) {
        float4 v = ((const float4*)x)[i];
        uint2 u;
        u.x = packh2(v.x, v.y);
        u.y = packh2(v.z, v.w);
        g_xh[i] = u;
    }
}

// ---------------- GEMM1 (tf32): z_h (nt=0), feat_h (nt=1..4) ----------------
__global__ void k_gemm1(const float* __restrict__ x,
                        const float* __restrict__ Wgm, const float* __restrict__ bgm,
                        const float* __restrict__ Wfc) {
    __shared__ unsigned As[128][20];
    __shared__ unsigned Bs[16][72];
    int t = threadIdx.x;
    int nt = blockIdx.y;
    int rowBase = blockIdx.x * 128;
    const float* W; int ldw, colBase;
    if (nt == 0) { W = Wgm; ldw = 64;  colBase = 0; }
    else         { W = Wfc; ldw = 256; colBase = (nt - 1) * 64; }

    int lane = t & 31, wrp = t >> 5;
    int wm = wrp & 3, wn = wrp >> 2;
    int g = lane >> 2, tig = lane & 3;

    float acc[2][4][4];
    #pragma unroll
    for (int mi = 0; mi < 2; mi++)
        #pragma unroll
        for (int ni = 0; ni < 4; ni++)
            #pragma unroll
            for (int q = 0; q < 4; q++) acc[mi][ni][q] = 0.f;

    int ar0 = t >> 2, akq = t & 3;
    int ar1 = ar0 + 64;
    int gr0 = rowBase + ar0; if (gr0 >= NN) gr0 = NN - 1;
    int gr1 = rowBase + ar1; if (gr1 >= NN) gr1 = NN - 1;
    int bk = t >> 4, bq = t & 15;

    for (int kt = 0; kt < 8; kt++) {
        float4 a0v = *(const float4*)&x[gr0 * IN_F + kt * 16 + akq * 4];
        float4 a1v = *(const float4*)&x[gr1 * IN_F + kt * 16 + akq * 4];
        float4 bv  = *(const float4*)&W[(kt * 16 + bk) * ldw + colBase + bq * 4];
        uint4 u0 = {f2tf(a0v.x), f2tf(a0v.y), f2tf(a0v.z), f2tf(a0v.w)};
        uint4 u1 = {f2tf(a1v.x), f2tf(a1v.y), f2tf(a1v.z), f2tf(a1v.w)};
        uint4 ub = {f2tf(bv.x),  f2tf(bv.y),  f2tf(bv.z),  f2tf(bv.w)};
        *(uint4*)&As[ar0][akq * 4] = u0;
        *(uint4*)&As[ar1][akq * 4] = u1;
        *(uint4*)&Bs[bk][bq * 4]   = ub;
        __syncthreads();
        #pragma unroll
        for (int ki = 0; ki < 2; ki++) {
            unsigned a[2][4];
            #pragma unroll
            for (int mi = 0; mi < 2; mi++) {
                int rm = wm * 32 + mi * 16;
                a[mi][0] = As[rm + g][ki * 8 + tig];
                a[mi][1] = As[rm + g + 8][ki * 8 + tig];
                a[mi][2] = As[rm + g][ki * 8 + tig + 4];
                a[mi][3] = As[rm + g + 8][ki * 8 + tig + 4];
            }
            #pragma unroll
            for (int ni = 0; ni < 4; ni++) {
                int cn = wn * 32 + ni * 8;
                unsigned b0 = Bs[ki * 8 + tig][cn + g];
                unsigned b1 = Bs[ki * 8 + tig + 4][cn + g];
                mma8(acc[0][ni], a[0][0], a[0][1], a[0][2], a[0][3], b0, b1);
                mma8(acc[1][ni], a[1][0], a[1][1], a[1][2], a[1][3], b0, b1);
            }
        }
        __syncthreads();
    }

    #pragma unroll
    for (int mi = 0; mi < 2; mi++) {
        #pragma unroll
        for (int ni = 0; ni < 4; ni++) {
            int lc = wn * 32 + ni * 8 + tig * 2;
            #pragma unroll
            for (int half = 0; half < 2; half++) {
                int r = rowBase + wm * 32 + mi * 16 + g + half * 8;
                if (r < NN) {
                    float v0 = acc[mi][ni][half * 2 + 0];
                    float v1 = acc[mi][ni][half * 2 + 1];
                    if (nt == 0) {
                        g_zh[r * 32 + (lc >> 1)] = packh2(v0 + bgm[lc], v1 + bgm[lc + 1]);
                    } else {
                        ((unsigned*)g_fh)[r * 128 + ((colBase + lc) >> 1)] = packh2(v0, v1);
                    }
                }
            }
        }
    }
}

// ---------------- el/er: per-node head dot products (fp16 feat) ----------------
__global__ void k_elr(const float* __restrict__ al, const float* __restrict__ ar) {
    int w = threadIdx.x >> 5, lane = threadIdx.x & 31;
    int nodeid = blockIdx.x * 8 + w;
    if (nodeid >= NN) return;
    int h1 = lane >> 4, q = lane & 15;
    uint2 ua = g_fh[nodeid * 64 + lane];
    uint2 ub = g_fh[nodeid * 64 + 32 + lane];
    float2 fa0 = unpackh2(ua.x), fa1 = unpackh2(ua.y);
    float2 fb0 = unpackh2(ub.x), fb1 = unpackh2(ub.y);
    const float4* al4 = (const float4*)al;
    const float4* ar4 = (const float4*)ar;
    float4 a0 = al4[h1 * 16 + q], a1 = al4[(h1 + 2) * 16 + q];
    float4 r0 = ar4[h1 * 16 + q], r1 = ar4[(h1 + 2) * 16 + q];
    float el0 = fa0.x * a0.x + fa0.y * a0.y + fa1.x * a0.z + fa1.y * a0.w;
    float el1 = fb0.x * a1.x + fb0.y * a1.y + fb1.x * a1.z + fb1.y * a1.w;
    float er0 = fa0.x * r0.x + fa0.y * r0.y + fa1.x * r0.z + fa1.y * r0.w;
    float er1 = fb0.x * r1.x + fb0.y * r1.y + fb1.x * r1.z + fb1.y * r1.w;
    #pragma unroll
    for (int d = 8; d >= 1; d >>= 1) {
        el0 += __shfl_down_sync(0xffffffffu, el0, d);
        el1 += __shfl_down_sync(0xffffffffu, el1, d);
        er0 += __shfl_down_sync(0xffffffffu, er0, d);
        er1 += __shfl_down_sync(0xffffffffu, er1, d);
    }
    if ((lane & 15) == 0) {
        g_el[nodeid * 4 + h1]     = el0;
        g_el[nodeid * 4 + h1 + 2] = el1;
        g_er[nodeid * 4 + h1]     = er0;
        g_er[nodeid * 4 + h1 + 2] = er1;
    }
}

// ---------------- fused single-pass agg, unroll-4 ------------------------------------
__global__ void k_agg(const float* __restrict__ x,
                      const float* __restrict__ Wg, const float* __restrict__ bg,
                      const float* __restrict__ bgat) {
    __shared__ float sWg[(2 * IN_F + MAPF) * NH];
    for (int i = threadIdx.x; i < (2 * IN_F + MAPF) * NH; i += blockDim.x) sWg[i] = Wg[i];
    __syncthreads();
    int w = threadIdx.x >> 5, lane = threadIdx.x & 31;
    int d = blockIdx.x * 8 + w;
    if (d >= NN) return;
    int o0 = g_off[d], o1 = g_off[d + 1];
    int deg = o1 - o0;

    const float4* el4p = (const float4*)g_el;
    float4 er4 = ((const float4*)g_er)[d];
    int h1 = lane >> 4, q = lane & 15;

    float4 s4 = {0.f, 0.f, 0.f, 0.f};
    float zmx = -1e30f, zmy = -1e30f;
    float den0 = 0.f, den1 = 0.f, den2 = 0.f, den3 = 0.f;
    float4 acc0 = {0.f, 0.f, 0.f, 0.f}, acc1 = {0.f, 0.f, 0.f, 0.f};

    int i = o0;
    for (; i + 3 < o1; i += 4) {
        int s[4];
        s[0] = g_srcs[i]; s[1] = g_srcs[i + 1]; s[2] = g_srcs[i + 2]; s[3] = g_srcs[i + 3];
        uint2 xh[4]; unsigned zu[4]; float4 ev[4]; uint2 ua[4], ub[4];
        #pragma unroll
        for (int j = 0; j < 4; j++) {
            xh[j] = g_xh[s[j] * 32 + lane];
            zu[j] = g_zh[s[j] * 32 + lane];
            ev[j] = el4p[s[j]];
            ua[j] = g_fh[s[j] * 64 + lane];
            ub[j] = g_fh[s[j] * 64 + 32 + lane];
        }
        #pragma unroll
        for (int j = 0; j < 4; j++) {
            float2 xa = unpackh2(xh[j].x), xb = unpackh2(xh[j].y);
            s4.x += xa.x; s4.y += xa.y; s4.z += xb.x; s4.w += xb.y;
            float2 zv = unpackh2(zu[j]);
            zmx = fmaxf(zmx, zv.x); zmy = fmaxf(zmy, zv.y);
            float e0 = ev[j].x + er4.x, e1 = ev[j].y + er4.y;
            float e2 = ev[j].z + er4.z, e3 = ev[j].w + er4.w;
            e0 = (e0 > 0.f) ? e0 : 0.2f * e0;
            e1 = (e1 > 0.f) ? e1 : 0.2f * e1;
            e2 = (e2 > 0.f) ? e2 : 0.2f * e2;
            e3 = (e3 > 0.f) ? e3 : 0.2f * e3;
            float w0 = __expf(e0), w1 = __expf(e1);
            float w2 = __expf(e2), w3 = __expf(e3);
            den0 += w0; den1 += w1; den2 += w2; den3 += w3;
            float2 fa0 = unpackh2(ua[j].x), fa1 = unpackh2(ua[j].y);
            float2 fb0 = unpackh2(ub[j].x), fb1 = unpackh2(ub[j].y);
            float wa = (h1 == 0) ? w0 : w1;
            float wb = (h1 == 0) ? w2 : w3;
            acc0.x += wa * fa0.x; acc0.y += wa * fa0.y; acc0.z += wa * fa1.x; acc0.w += wa * fa1.y;
            acc1.x += wb * fb0.x; acc1.y += wb * fb0.y; acc1.z += wb * fb1.x; acc1.w += wb * fb1.y;
        }
    }
    for (; i < o1; i++) {
        int s0 = g_srcs[i];
        uint2 xh0 = g_xh[s0 * 32 + lane];
        unsigned zu0 = g_zh[s0 * 32 + lane];
        float4 ev0 = el4p[s0];
        uint2 ua0 = g_fh[s0 * 64 + lane];
        uint2 ub0 = g_fh[s0 * 64 + 32 + lane];
        float2 xa = unpackh2(xh0.x), xb = unpackh2(xh0.y);
        s4.x += xa.x; s4.y += xa.y; s4.z += xb.x; s4.w += xb.y;
        float2 zv = unpackh2(zu0);
        zmx = fmaxf(zmx, zv.x); zmy = fmaxf(zmy, zv.y);
        float e0 = ev0.x + er4.x, e1 = ev0.y + er4.y;
        float e2 = ev0.z + er4.z, e3 = ev0.w + er4.w;
        e0 = (e0 > 0.f) ? e0 : 0.2f * e0;
        e1 = (e1 > 0.f) ? e1 : 0.2f * e1;
        e2 = (e2 > 0.f) ? e2 : 0.2f * e2;
        e3 = (e3 > 0.f) ? e3 : 0.2f * e3;
        float w0 = __expf(e0), w1 = __expf(e1);
        float w2 = __expf(e2), w3 = __expf(e3);
        den0 += w0; den1 += w1; den2 += w2; den3 += w3;
        float2 fa0 = unpackh2(ua0.x), fa1 = unpackh2(ua0.y);
        float2 fb0 = unpackh2(ub0.x), fb1 = unpackh2(ub0.y);
        float wa = (h1 == 0) ? w0 : w1;
        float wb = (h1 == 0) ? w2 : w3;
        acc0.x += wa * fa0.x; acc0.y += wa * fa0.y; acc0.z += wa * fa1.x; acc0.w += wa * fa1.y;
        acc1.x += wb * fb0.x; acc1.y += wb * fb0.y; acc1.z += wb * fb1.x; acc1.w += wb * fb1.y;
    }

    // ---- gate from mean/max ----
    float inv = (deg > 0) ? 1.0f / (float)deg : 0.0f;
    float4 mean = {s4.x * inv, s4.y * inv, s4.z * inv, s4.w * inv};
    if (deg == 0) { zmx = 0.f; zmy = 0.f; }
    float4 xd = ((const float4*)x)[d * 32 + lane];
    float p[4];
    #pragma unroll
    for (int h = 0; h < 4; h++) {
        int r0 = 4 * lane;
        float v = xd.x * sWg[(r0 + 0) * 4 + h] + xd.y * sWg[(r0 + 1) * 4 + h]
                + xd.z * sWg[(r0 + 2) * 4 + h] + xd.w * sWg[(r0 + 3) * 4 + h];
        int r1 = IN_F + 2 * lane;
        v += zmx * sWg[(r1 + 0) * 4 + h] + zmy * sWg[(r1 + 1) * 4 + h];
        int r2 = IN_F + MAPF + 4 * lane;
        v += mean.x * sWg[(r2 + 0) * 4 + h] + mean.y * sWg[(r2 + 1) * 4 + h]
           + mean.z * sWg[(r2 + 2) * 4 + h] + mean.w * sWg[(r2 + 3) * 4 + h];
        p[h] = v;
    }
    #pragma unroll
    for (int dd = 16; dd >= 1; dd >>= 1) {
        #pragma unroll
        for (int h = 0; h < 4; h++) p[h] += __shfl_xor_sync(0xffffffffu, p[h], dd);
    }
    float gate[4];
    #pragma unroll
    for (int h = 0; h < 4; h++) gate[h] = 1.f / (1.f + __expf(-(p[h] + bg[h])));

    // ---- normalize, bias, gate, head-average, store ----
    float4 bga = ((const float4*)bgat)[h1 * 16 + q];
    float4 bgb = ((const float4*)bgat)[(h1 + 2) * 16 + q];
    float4 a0, a1;
    if (deg > 0) {
        float ia = 1.f / ((h1 == 0) ? den0 : den1);
        float ib = 1.f / ((h1 == 0) ? den2 : den3);
        a0.x = acc0.x * ia + bga.x; a0.y = acc0.y * ia + bga.y;
        a0.z = acc0.z * ia + bga.z; a0.w = acc0.w * ia + bga.w;
        a1.x = acc1.x * ib + bgb.x; a1.y = acc1.y * ib + bgb.y;
        a1.z = acc1.z * ib + bgb.z; a1.w = acc1.w * ib + bgb.w;
    } else {
        a0 = bga; a1 = bgb;
    }
    float g0 = (h1 == 0) ? gate[0] : gate[1];
    float g1 = (h1 == 0) ? gate[2] : gate[3];
    float4 pp;
    pp.x = g0 * a0.x + g1 * a1.x;
    pp.y = g0 * a0.y + g1 * a1.y;
    pp.z = g0 * a0.z + g1 * a1.z;
    pp.w = g0 * a0.w + g1 * a1.w;
    pp.x += __shfl_xor_sync(0xffffffffu, pp.x, 16);
    pp.y += __shfl_xor_sync(0xffffffffu, pp.y, 16);
    pp.z += __shfl_xor_sync(0xffffffffu, pp.z, 16);
    pp.w += __shfl_xor_sync(0xffffffffu, pp.w, 16);
    pp.x *= 0.25f; pp.y *= 0.25f; pp.z *= 0.25f; pp.w *= 0.25f;
    if (lane < 16) ((float4*)g_gated)[d * 16 + lane] = pp;
}

// ---------------- merge GEMM (tf32): out = [x | gated] @ W_merge + b_merge ------------
__global__ void k_merge(const float* __restrict__ x, const float* __restrict__ Wm,
                        const float* __restrict__ bm, float* __restrict__ out) {
    __shared__ unsigned As[128][20];
    __shared__ unsigned Bs[16][72];
    int t = threadIdx.x;
    int rowBase = blockIdx.x * 128;
    int lane = t & 31, wrp = t >> 5;
    int wm = wrp & 3, wn = wrp >> 2;
    int g = lane >> 2, tig = lane & 3;

    float acc[2][4][4];
    #pragma unroll
    for (int mi = 0; mi < 2; mi++)
        #pragma unroll
        for (int ni = 0; ni < 4; ni++)
            #pragma unroll
            for (int q = 0; q < 4; q++) acc[mi][ni][q] = 0.f;

    int ar0 = t >> 2, akq = t & 3;
    int ar1 = ar0 + 64;
    int gr0 = rowBase + ar0; if (gr0 >= NN) gr0 = NN - 1;
    int gr1 = rowBase + ar1; if (gr1 >= NN) gr1 = NN - 1;
    int bk = t >> 4, bq = t & 15;

    for (int kt = 0; kt < 12; kt++) {
        int k0 = kt * 16 + akq * 4;
        float4 a0v, a1v;
        if (k0 < IN_F) {
            a0v = *(const float4*)&x[gr0 * IN_F + k0];
            a1v = *(const float4*)&x[gr1 * IN_F + k0];
        } else {
            a0v = *(const float4*)&g_gated[gr0 * OUT_F + (k0 - IN_F)];
            a1v = *(const float4*)&g_gated[gr1 * OUT_F + (k0 - IN_F)];
        }
        float4 bv = *(const float4*)&Wm[(kt * 16 + bk) * 64 + bq * 4];
        uint4 u0 = {f2tf(a0v.x), f2tf(a0v.y), f2tf(a0v.z), f2tf(a0v.w)};
        uint4 u1 = {f2tf(a1v.x), f2tf(a1v.y), f2tf(a1v.z), f2tf(a1v.w)};
        uint4 ub = {f2tf(bv.x),  f2tf(bv.y),  f2tf(bv.z),  f2tf(bv.w)};
        *(uint4*)&As[ar0][akq * 4] = u0;
        *(uint4*)&As[ar1][akq * 4] = u1;
        *(uint4*)&Bs[bk][bq * 4]   = ub;
        __syncthreads();
        #pragma unroll
        for (int ki = 0; ki < 2; ki++) {
            unsigned a[2][4];
            #pragma unroll
            for (int mi = 0; mi < 2; mi++) {
                int rm = wm * 32 + mi * 16;
                a[mi][0] = As[rm + g][ki * 8 + tig];
                a[mi][1] = As[rm + g + 8][ki * 8 + tig];
                a[mi][2] = As[rm + g][ki * 8 + tig + 4];
                a[mi][3] = As[rm + g + 8][ki * 8 + tig + 4];
            }
            #pragma unroll
            for (int ni = 0; ni < 4; ni++) {
                int cn = wn * 32 + ni * 8;
                unsigned b0 = Bs[ki * 8 + tig][cn + g];
                unsigned b1 = Bs[ki * 8 + tig + 4][cn + g];
                mma8(acc[0][ni], a[0][0], a[0][1], a[0][2], a[0][3], b0, b1);
                mma8(acc[1][ni], a[1][0], a[1][1], a[1][2], a[1][3], b0, b1);
            }
        }
        __syncthreads();
    }

    #pragma unroll
    for (int mi = 0; mi < 2; mi++) {
        #pragma unroll
        for (int ni = 0; ni < 4; ni++) {
            int lc = wn * 32 + ni * 8 + tig * 2;
            #pragma unroll
            for (int half = 0; half < 2; half++) {
                int r = rowBase + wm * 32 + mi * 16 + g + half * 8;
                if (r < NN) {
                    out[r * OUT_F + lc]     = acc[mi][ni][half * 2 + 0] + bm[lc];
                    out[r * OUT_F + lc + 1] = acc[mi][ni][half * 2 + 1] + bm[lc + 1];
                }
            }
        }
    }
}

// ---------------- launch ----------------
extern "C" void kernel_launch(void* const* d_in, const int* in_sizes, int n_in,
                              void* d_out, int out_size) {
    const float* x      = (const float*)d_in[0];
    const int*   ei     = (const int*)d_in[1];
    const float* W_gm   = (const float*)d_in[2];
    const float* b_gm   = (const float*)d_in[3];
    const float* W_gate = (const float*)d_in[4];
    const float* b_gate = (const float*)d_in[5];
    const float* W_fc   = (const float*)d_in[6];
    const float* attn_l = (const float*)d_in[7];
    const float* attn_r = (const float*)d_in[8];
    const float* b_gat  = (const float*)d_in[9];
    const float* W_mrg  = (const float*)d_in[10];
    const float* b_mrg  = (const float*)d_in[11];
    float* out = (float*)d_out;

    const int* src = ei;
    const int* dst = ei + EE;

    k_zero<<<(NN + 255) / 256, 256>>>();
    k_hist<<<(EE / 4 + 255) / 256, 256>>>(dst);
    k_scan1<<<NB, SCAN_BS>>>();
    k_scan2<<<1, 128>>>();
    k_scan3<<<NB, SCAN_BS>>>();
    k_scatter<<<(EE / 4 + 255) / 256, 256>>>(src, dst);
    k_xhalf<<<(NN * 32 + 255) / 256, 256>>>(x);
    k_gemm1<<<dim3((NN + 127) / 128, 5), 256>>>(x, W_gm, b_gm, W_fc);
    k_elr<<<(NN + 7) / 8, 256>>>(attn_l, attn_r);
    k_agg<<<(NN + 7) / 8, 256>>>(x, W_gate, b_gate, b_gat);
    k_merge<<<(NN + 127) / 128, 256>>>(x, W_mrg, b_mrg, out);
}

// round 7
// speedup vs baseline: 1.6381x; 1.0069x over previous
#include <cuda_runtime.h>
#include <cuda_fp16.h>

#define NN   50000
#define EE   800000
#define IN_F 128
#define OUT_F 64
#define MAPF 64
#define NH   4
#define SCAN_BS 512
#define NB ((NN + SCAN_BS - 1) / SCAN_BS)   // 98

// ---------------- scratch (static device globals; no allocation) ----------------
__device__ int   g_count[NN];
__device__ int   g_off[NN + 1];
__device__ int   g_cursor[NN];
__device__ int   g_bsum[NB];
__device__ int   g_bbase[NB];
__device__ int   g_srcs[EE];
__device__ unsigned g_zh[NN * 32];   // z as fp16: 64 halfs/row
__device__ uint2    g_fh[NN * 64];   // feat as fp16: 256 halfs/row ([h][64])
__device__ float4 g_eg[NN * 2];      // [2n] = el(4 heads), [2n+1] = gx3 = x@W_gate[192:320]
__device__ float4 g_er4[NN];         // er (4 heads)
__device__ float4 g_gx1[NN];         // x@W_gate[0:128]
__device__ float g_gated[NN * OUT_F];

// ---------------- helpers ----------------
__device__ __forceinline__ unsigned f2tf(float f) {
    unsigned u;
    asm("cvt.rna.tf32.f32 %0, %1;" : "=r"(u) : "f"(f));
    return u;
}
__device__ __forceinline__ void mma8(float* c, unsigned a0, unsigned a1, unsigned a2,
                                     unsigned a3, unsigned b0, unsigned b1) {
    asm volatile(
        "mma.sync.aligned.m16n8k8.row.col.f32.tf32.tf32.f32 "
        "{%0,%1,%2,%3},{%4,%5,%6,%7},{%8,%9},{%0,%1,%2,%3};"
        : "+f"(c[0]), "+f"(c[1]), "+f"(c[2]), "+f"(c[3])
        : "r"(a0), "r"(a1), "r"(a2), "r"(a3), "r"(b0), "r"(b1));
}
__device__ __forceinline__ unsigned packh2(float a, float b) {
    __half2 h = __floats2half2_rn(a, b);
    return *(unsigned*)&h;
}
__device__ __forceinline__ float2 unpackh2(unsigned u) {
    return __half22float2(*(__half2*)&u);
}

// ---------------- CSR build ----------------
__global__ void k_zero() {
    int i = blockIdx.x * blockDim.x + threadIdx.x;
    if (i < NN) g_count[i] = 0;
}

__global__ void k_hist(const int* __restrict__ dst) {
    int e4 = blockIdx.x * blockDim.x + threadIdx.x;
    if (e4 < EE / 4) {
        int4 d = ((const int4*)dst)[e4];
        atomicAdd(&g_count[d.x], 1);
        atomicAdd(&g_count[d.y], 1);
        atomicAdd(&g_count[d.z], 1);
        atomicAdd(&g_count[d.w], 1);
    }
}

__global__ void k_scan1() {
    __shared__ int wsum[16];
    int b = blockIdx.x, t = threadIdx.x, lane = t & 31, w = t >> 5;
    int i = b * SCAN_BS + t;
    int v = (i < NN) ? g_count[i] : 0;
    int xs = v;
    #pragma unroll
    for (int d = 1; d < 32; d <<= 1) {
        int y = __shfl_up_sync(0xffffffffu, xs, d);
        if (lane >= d) xs += y;
    }
    if (lane == 31) wsum[w] = xs;
    __syncthreads();
    if (w == 0) {
        int s = (lane < 16) ? wsum[lane] : 0;
        #pragma unroll
        for (int d = 1; d < 16; d <<= 1) {
            int y = __shfl_up_sync(0xffffffffu, s, d);
            if (lane >= d) s += y;
        }
        if (lane < 16) wsum[lane] = s;
    }
    __syncthreads();
    int base = (w > 0) ? wsum[w - 1] : 0;
    if (i < NN) g_off[i] = base + xs - v;
    if (t == SCAN_BS - 1) g_bsum[b] = wsum[15];
}

__global__ void k_scan2() {
    __shared__ int ws[4];
    int t = threadIdx.x, lane = t & 31, w = t >> 5;
    int v = (t < NB) ? g_bsum[t] : 0;
    int xs = v;
    #pragma unroll
    for (int d = 1; d < 32; d <<= 1) {
        int y = __shfl_up_sync(0xffffffffu, xs, d);
        if (lane >= d) xs += y;
    }
    if (lane == 31) ws[w] = xs;
    __syncthreads();
    if (t == 0) {
        int a = 0;
        #pragma unroll
        for (int k = 0; k < 4; k++) { int tmp = ws[k]; ws[k] = a; a += tmp; }
    }
    __syncthreads();
    if (t < NB) g_bbase[t] = ws[w] + xs - v;
}

__global__ void k_scan3() {
    int b = blockIdx.x, t = threadIdx.x;
    int i = b * SCAN_BS + t;
    if (i < NN) {
        int o = g_off[i] + g_bbase[b];
        g_off[i] = o;
        g_cursor[i] = o;
    }
    if (i == 0) g_off[NN] = EE;
}

__global__ void k_scatter(const int* __restrict__ src, const int* __restrict__ dst) {
    int e4 = blockIdx.x * blockDim.x + threadIdx.x;
    if (e4 < EE / 4) {
        int4 d = ((const int4*)dst)[e4];
        int4 s = ((const int4*)src)[e4];
        g_srcs[atomicAdd(&g_cursor[d.x], 1)] = s.x;
        g_srcs[atomicAdd(&g_cursor[d.y], 1)] = s.y;
        g_srcs[atomicAdd(&g_cursor[d.z], 1)] = s.z;
        g_srcs[atomicAdd(&g_cursor[d.w], 1)] = s.w;
    }
}

// ---------------- GEMM1 (tf32): z_h (nt=0), feat_h (nt=1..4) ----------------
__global__ void k_gemm1(const float* __restrict__ x,
                        const float* __restrict__ Wgm, const float* __restrict__ bgm,
                        const float* __restrict__ Wfc) {
    __shared__ unsigned As[128][20];
    __shared__ unsigned Bs[16][72];
    int t = threadIdx.x;
    int nt = blockIdx.y;
    int rowBase = blockIdx.x * 128;
    const float* W; int ldw, colBase;
    if (nt == 0) { W = Wgm; ldw = 64;  colBase = 0; }
    else         { W = Wfc; ldw = 256; colBase = (nt - 1) * 64; }

    int lane = t & 31, wrp = t >> 5;
    int wm = wrp & 3, wn = wrp >> 2;
    int g = lane >> 2, tig = lane & 3;

    float acc[2][4][4];
    #pragma unroll
    for (int mi = 0; mi < 2; mi++)
        #pragma unroll
        for (int ni = 0; ni < 4; ni++)
            #pragma unroll
            for (int q = 0; q < 4; q++) acc[mi][ni][q] = 0.f;

    int ar0 = t >> 2, akq = t & 3;
    int ar1 = ar0 + 64;
    int gr0 = rowBase + ar0; if (gr0 >= NN) gr0 = NN - 1;
    int gr1 = rowBase + ar1; if (gr1 >= NN) gr1 = NN - 1;
    int bk = t >> 4, bq = t & 15;

    for (int kt = 0; kt < 8; kt++) {
        float4 a0v = *(const float4*)&x[gr0 * IN_F + kt * 16 + akq * 4];
        float4 a1v = *(const float4*)&x[gr1 * IN_F + kt * 16 + akq * 4];
        float4 bv  = *(const float4*)&W[(kt * 16 + bk) * ldw + colBase + bq * 4];
        uint4 u0 = {f2tf(a0v.x), f2tf(a0v.y), f2tf(a0v.z), f2tf(a0v.w)};
        uint4 u1 = {f2tf(a1v.x), f2tf(a1v.y), f2tf(a1v.z), f2tf(a1v.w)};
        uint4 ub = {f2tf(bv.x),  f2tf(bv.y),  f2tf(bv.z),  f2tf(bv.w)};
        *(uint4*)&As[ar0][akq * 4] = u0;
        *(uint4*)&As[ar1][akq * 4] = u1;
        *(uint4*)&Bs[bk][bq * 4]   = ub;
        __syncthreads();
        #pragma unroll
        for (int ki = 0; ki < 2; ki++) {
            unsigned a[2][4];
            #pragma unroll
            for (int mi = 0; mi < 2; mi++) {
                int rm = wm * 32 + mi * 16;
                a[mi][0] = As[rm + g][ki * 8 + tig];
                a[mi][1] = As[rm + g + 8][ki * 8 + tig];
                a[mi][2] = As[rm + g][ki * 8 + tig + 4];
                a[mi][3] = As[rm + g + 8][ki * 8 + tig + 4];
            }
            #pragma unroll
            for (int ni = 0; ni < 4; ni++) {
                int cn = wn * 32 + ni * 8;
                unsigned b0 = Bs[ki * 8 + tig][cn + g];
                unsigned b1 = Bs[ki * 8 + tig + 4][cn + g];
                mma8(acc[0][ni], a[0][0], a[0][1], a[0][2], a[0][3], b0, b1);
                mma8(acc[1][ni], a[1][0], a[1][1], a[1][2], a[1][3], b0, b1);
            }
        }
        __syncthreads();
    }

    #pragma unroll
    for (int mi = 0; mi < 2; mi++) {
        #pragma unroll
        for (int ni = 0; ni < 4; ni++) {
            int lc = wn * 32 + ni * 8 + tig * 2;
            #pragma unroll
            for (int half = 0; half < 2; half++) {
                int r = rowBase + wm * 32 + mi * 16 + g + half * 8;
                if (r < NN) {
                    float v0 = acc[mi][ni][half * 2 + 0];
                    float v1 = acc[mi][ni][half * 2 + 1];
                    if (nt == 0) {
                        g_zh[r * 32 + (lc >> 1)] = packh2(v0 + bgm[lc], v1 + bgm[lc + 1]);
                    } else {
                        ((unsigned*)g_fh)[r * 128 + ((colBase + lc) >> 1)] = packh2(v0, v1);
                    }
                }
            }
        }
    }
}

// ---------------- k_pre: el/er + gx1/gx3 per node (warp per node) ----------------
__global__ void k_pre(const float* __restrict__ x,
                      const float* __restrict__ al, const float* __restrict__ ar,
                      const float* __restrict__ Wg) {
    __shared__ float sW1[IN_F * NH];   // W_gate rows 0..127
    __shared__ float sW3[IN_F * NH];   // W_gate rows 192..319
    for (int i = threadIdx.x; i < IN_F * NH; i += blockDim.x) {
        sW1[i] = Wg[i];
        sW3[i] = Wg[192 * NH + i];     // rows 192..319 start at element 192*4=768
    }
    __syncthreads();
    int w = threadIdx.x >> 5, lane = threadIdx.x & 31;
    int n = blockIdx.x * 8 + w;
    if (n >= NN) return;
    int h1 = lane >> 4, q = lane & 15;

    uint2 ua = g_fh[n * 64 + lane];
    uint2 ub = g_fh[n * 64 + 32 + lane];
    float2 fa0 = unpackh2(ua.x), fa1 = unpackh2(ua.y);
    float2 fb0 = unpackh2(ub.x), fb1 = unpackh2(ub.y);
    const float4* al4 = (const float4*)al;
    const float4* ar4 = (const float4*)ar;
    float4 a0 = al4[h1 * 16 + q], a1 = al4[(h1 + 2) * 16 + q];
    float4 r0 = ar4[h1 * 16 + q], r1 = ar4[(h1 + 2) * 16 + q];
    float el0 = fa0.x * a0.x + fa0.y * a0.y + fa1.x * a0.z + fa1.y * a0.w;
    float el1 = fb0.x * a1.x + fb0.y * a1.y + fb1.x * a1.z + fb1.y * a1.w;
    float er0 = fa0.x * r0.x + fa0.y * r0.y + fa1.x * r0.z + fa1.y * r0.w;
    float er1 = fb0.x * r1.x + fb0.y * r1.y + fb1.x * r1.z + fb1.y * r1.w;

    float4 xv = ((const float4*)x)[n * 32 + lane];
    float gx1[4], gx3[4];
    int r = 4 * lane;
    #pragma unroll
    for (int h = 0; h < 4; h++) {
        gx1[h] = xv.x * sW1[(r + 0) * 4 + h] + xv.y * sW1[(r + 1) * 4 + h]
               + xv.z * sW1[(r + 2) * 4 + h] + xv.w * sW1[(r + 3) * 4 + h];
        gx3[h] = xv.x * sW3[(r + 0) * 4 + h] + xv.y * sW3[(r + 1) * 4 + h]
               + xv.z * sW3[(r + 2) * 4 + h] + xv.w * sW3[(r + 3) * 4 + h];
    }

    #pragma unroll
    for (int d = 8; d >= 1; d >>= 1) {
        el0 += __shfl_down_sync(0xffffffffu, el0, d);
        el1 += __shfl_down_sync(0xffffffffu, el1, d);
        er0 += __shfl_down_sync(0xffffffffu, er0, d);
        er1 += __shfl_down_sync(0xffffffffu, er1, d);
    }
    #pragma unroll
    for (int d = 16; d >= 1; d >>= 1) {
        #pragma unroll
        for (int h = 0; h < 4; h++) {
            gx1[h] += __shfl_xor_sync(0xffffffffu, gx1[h], d);
            gx3[h] += __shfl_xor_sync(0xffffffffu, gx3[h], d);
        }
    }
    float elh1 = __shfl_sync(0xffffffffu, el0, 16);
    float elh3 = __shfl_sync(0xffffffffu, el1, 16);
    float erh1 = __shfl_sync(0xffffffffu, er0, 16);
    float erh3 = __shfl_sync(0xffffffffu, er1, 16);
    if (lane == 0) {
        g_eg[2 * n]     = make_float4(el0, elh1, el1, elh3);
        g_eg[2 * n + 1] = make_float4(gx3[0], gx3[1], gx3[2], gx3[3]);
        g_er4[n]        = make_float4(er0, erh1, er1, erh3);
        g_gx1[n]        = make_float4(gx1[0], gx1[1], gx1[2], gx1[3]);
    }
}

// ---------------- fused single-pass agg, unroll-4, reduced traffic --------------------
__global__ void k_agg(const float* __restrict__ Wg, const float* __restrict__ bg,
                      const float* __restrict__ bgat) {
    __shared__ float sW2[MAPF * NH];   // W_gate rows 128..191
    for (int i = threadIdx.x; i < MAPF * NH; i += blockDim.x) sW2[i] = Wg[IN_F * NH + i];
    __syncthreads();
    int w = threadIdx.x >> 5, lane = threadIdx.x & 31;
    int d = blockIdx.x * 8 + w;
    if (d >= NN) return;
    int o0 = g_off[d], o1 = g_off[d + 1];
    int deg = o1 - o0;

    float4 er4 = g_er4[d];
    float4 gx1d = g_gx1[d];
    int h1 = lane >> 4, q = lane & 15;

    float zmx = -1e30f, zmy = -1e30f;
    float gxs0 = 0.f, gxs1 = 0.f, gxs2 = 0.f, gxs3 = 0.f;
    float den0 = 0.f, den1 = 0.f, den2 = 0.f, den3 = 0.f;
    float4 acc0 = {0.f, 0.f, 0.f, 0.f}, acc1 = {0.f, 0.f, 0.f, 0.f};

    int i = o0;
    for (; i + 3 < o1; i += 4) {
        int s[4];
        s[0] = g_srcs[i]; s[1] = g_srcs[i + 1]; s[2] = g_srcs[i + 2]; s[3] = g_srcs[i + 3];
        unsigned zu[4]; float4 ev[4], g3[4]; uint2 ua[4], ub[4];
        #pragma unroll
        for (int j = 0; j < 4; j++) {
            zu[j] = g_zh[s[j] * 32 + lane];
            ev[j] = g_eg[2 * s[j]];
            g3[j] = g_eg[2 * s[j] + 1];
            ua[j] = g_fh[s[j] * 64 + lane];
            ub[j] = g_fh[s[j] * 64 + 32 + lane];
        }
        #pragma unroll
        for (int j = 0; j < 4; j++) {
            float2 zv = unpackh2(zu[j]);
            zmx = fmaxf(zmx, zv.x); zmy = fmaxf(zmy, zv.y);
            gxs0 += g3[j].x; gxs1 += g3[j].y; gxs2 += g3[j].z; gxs3 += g3[j].w;
            float e0 = ev[j].x + er4.x, e1 = ev[j].y + er4.y;
            float e2 = ev[j].z + er4.z, e3 = ev[j].w + er4.w;
            e0 = (e0 > 0.f) ? e0 : 0.2f * e0;
            e1 = (e1 > 0.f) ? e1 : 0.2f * e1;
            e2 = (e2 > 0.f) ? e2 : 0.2f * e2;
            e3 = (e3 > 0.f) ? e3 : 0.2f * e3;
            float w0 = __expf(e0), w1 = __expf(e1);
            float w2 = __expf(e2), w3 = __expf(e3);
            den0 += w0; den1 += w1; den2 += w2; den3 += w3;
            float2 fa0 = unpackh2(ua[j].x), fa1 = unpackh2(ua[j].y);
            float2 fb0 = unpackh2(ub[j].x), fb1 = unpackh2(ub[j].y);
            float wa = (h1 == 0) ? w0 : w1;
            float wb = (h1 == 0) ? w2 : w3;
            acc0.x += wa * fa0.x; acc0.y += wa * fa0.y; acc0.z += wa * fa1.x; acc0.w += wa * fa1.y;
            acc1.x += wb * fb0.x; acc1.y += wb * fb0.y; acc1.z += wb * fb1.x; acc1.w += wb * fb1.y;
        }
    }
    for (; i < o1; i++) {
        int s0 = g_srcs[i];
        unsigned zu0 = g_zh[s0 * 32 + lane];
        float4 ev0 = g_eg[2 * s0];
        float4 g30 = g_eg[2 * s0 + 1];
        uint2 ua0 = g_fh[s0 * 64 + lane];
        uint2 ub0 = g_fh[s0 * 64 + 32 + lane];
        float2 zv = unpackh2(zu0);
        zmx = fmaxf(zmx, zv.x); zmy = fmaxf(zmy, zv.y);
        gxs0 += g30.x; gxs1 += g30.y; gxs2 += g30.z; gxs3 += g30.w;
        float e0 = ev0.x + er4.x, e1 = ev0.y + er4.y;
        float e2 = ev0.z + er4.z, e3 = ev0.w + er4.w;
        e0 = (e0 > 0.f) ? e0 : 0.2f * e0;
        e1 = (e1 > 0.f) ? e1 : 0.2f * e1;
        e2 = (e2 > 0.f) ? e2 : 0.2f * e2;
        e3 = (e3 > 0.f) ? e3 : 0.2f * e3;
        float w0 = __expf(e0), w1 = __expf(e1);
        float w2 = __expf(e2), w3 = __expf(e3);
        den0 += w0; den1 += w1; den2 += w2; den3 += w3;
        float2 fa0 = unpackh2(ua0.x), fa1 = unpackh2(ua0.y);
        float2 fb0 = unpackh2(ub0.x), fb1 = unpackh2(ub0.y);
        float wa = (h1 == 0) ? w0 : w1;
        float wb = (h1 == 0) ? w2 : w3;
        acc0.x += wa * fa0.x; acc0.y += wa * fa0.y; acc0.z += wa * fa1.x; acc0.w += wa * fa1.y;
        acc1.x += wb * fb0.x; acc1.y += wb * fb0.y; acc1.z += wb * fb1.x; acc1.w += wb * fb1.y;
    }

    // ---- gate ----
    float inv = (deg > 0) ? 1.0f / (float)deg : 0.0f;
    if (deg == 0) { zmx = 0.f; zmy = 0.f; }
    float zr[4];
    int r2 = 2 * lane;
    #pragma unroll
    for (int h = 0; h < 4; h++)
        zr[h] = zmx * sW2[(r2 + 0) * 4 + h] + zmy * sW2[(r2 + 1) * 4 + h];
    #pragma unroll
    for (int dd = 16; dd >= 1; dd >>= 1) {
        #pragma unroll
        for (int h = 0; h < 4; h++) zr[h] += __shfl_xor_sync(0xffffffffu, zr[h], dd);
    }
    float gxs[4] = {gxs0, gxs1, gxs2, gxs3};
    float gx1a[4] = {gx1d.x, gx1d.y, gx1d.z, gx1d.w};
    float gate[4];
    #pragma unroll
    for (int h = 0; h < 4; h++) {
        float p = gx1a[h] + gxs[h] * inv + zr[h] + bg[h];
        gate[h] = 1.f / (1.f + __expf(-p));
    }

    // ---- normalize, bias, gate, head-average, store ----
    float4 bga = ((const float4*)bgat)[h1 * 16 + q];
    float4 bgb = ((const float4*)bgat)[(h1 + 2) * 16 + q];
    float4 a0, a1;
    if (deg > 0) {
        float ia = 1.f / ((h1 == 0) ? den0 : den1);
        float ib = 1.f / ((h1 == 0) ? den2 : den3);
        a0.x = acc0.x * ia + bga.x; a0.y = acc0.y * ia + bga.y;
        a0.z = acc0.z * ia + bga.z; a0.w = acc0.w * ia + bga.w;
        a1.x = acc1.x * ib + bgb.x; a1.y = acc1.y * ib + bgb.y;
        a1.z = acc1.z * ib + bgb.z; a1.w = acc1.w * ib + bgb.w;
    } else {
        a0 = bga; a1 = bgb;
    }
    float g0 = (h1 == 0) ? gate[0] : gate[1];
    float g1 = (h1 == 0) ? gate[2] : gate[3];
    float4 pp;
    pp.x = g0 * a0.x + g1 * a1.x;
    pp.y = g0 * a0.y + g1 * a1.y;
    pp.z = g0 * a0.z + g1 * a1.z;
    pp.w = g0 * a0.w + g1 * a1.w;
    pp.x += __shfl_xor_sync(0xffffffffu, pp.x, 16);
    pp.y += __shfl_xor_sync(0xffffffffu, pp.y, 16);
    pp.z += __shfl_xor_sync(0xffffffffu, pp.z, 16);
    pp.w += __shfl_xor_sync(0xffffffffu, pp.w, 16);
    pp.x *= 0.25f; pp.y *= 0.25f; pp.z *= 0.25f; pp.w *= 0.25f;
    if (lane < 16) ((float4*)g_gated)[d * 16 + lane] = pp;
}

// ---------------- merge GEMM (tf32): out = [x | gated] @ W_merge + b_merge ------------
__global__ void k_merge(const float* __restrict__ x, const float* __restrict__ Wm,
                        const float* __restrict__ bm, float* __restrict__ out) {
    __shared__ unsigned As[128][20];
    __shared__ unsigned Bs[16][72];
    int t = threadIdx.x;
    int rowBase = blockIdx.x * 128;
    int lane = t & 31, wrp = t >> 5;
    int wm = wrp & 3, wn = wrp >> 2;
    int g = lane >> 2, tig = lane & 3;

    float acc[2][4][4];
    #pragma unroll
    for (int mi = 0; mi < 2; mi++)
        #pragma unroll
        for (int ni = 0; ni < 4; ni++)
            #pragma unroll
            for (int q = 0; q < 4; q++) acc[mi][ni][q] = 0.f;

    int ar0 = t >> 2, akq = t & 3;
    int ar1 = ar0 + 64;
    int gr0 = rowBase + ar0; if (gr0 >= NN) gr0 = NN - 1;
    int gr1 = rowBase + ar1; if (gr1 >= NN) gr1 = NN - 1;
    int bk = t >> 4, bq = t & 15;

    for (int kt = 0; kt < 12; kt++) {
        int k0 = kt * 16 + akq * 4;
        float4 a0v, a1v;
        if (k0 < IN_F) {
            a0v = *(const float4*)&x[gr0 * IN_F + k0];
            a1v = *(const float4*)&x[gr1 * IN_F + k0];
        } else {
            a0v = *(const float4*)&g_gated[gr0 * OUT_F + (k0 - IN_F)];
            a1v = *(const float4*)&g_gated[gr1 * OUT_F + (k0 - IN_F)];
        }
        float4 bv = *(const float4*)&Wm[(kt * 16 + bk) * 64 + bq * 4];
        uint4 u0 = {f2tf(a0v.x), f2tf(a0v.y), f2tf(a0v.z), f2tf(a0v.w)};
        uint4 u1 = {f2tf(a1v.x), f2tf(a1v.y), f2tf(a1v.z), f2tf(a1v.w)};
        uint4 ub = {f2tf(bv.x),  f2tf(bv.y),  f2tf(bv.z),  f2tf(bv.w)};
        *(uint4*)&As[ar0][akq * 4] = u0;
        *(uint4*)&As[ar1][akq * 4] = u1;
        *(uint4*)&Bs[bk][bq * 4]   = ub;
        __syncthreads();
        #pragma unroll
        for (int ki = 0; ki < 2; ki++) {
            unsigned a[2][4];
            #pragma unroll
            for (int mi = 0; mi < 2; mi++) {
                int rm = wm * 32 + mi * 16;
                a[mi][0] = As[rm + g][ki * 8 + tig];
                a[mi][1] = As[rm + g + 8][ki * 8 + tig];
                a[mi][2] = As[rm + g][ki * 8 + tig + 4];
                a[mi][3] = As[rm + g + 8][ki * 8 + tig + 4];
            }
            #pragma unroll
            for (int ni = 0; ni < 4; ni++) {
                int cn = wn * 32 + ni * 8;
                unsigned b0 = Bs[ki * 8 + tig][cn + g];
                unsigned b1 = Bs[ki * 8 + tig + 4][cn + g];
                mma8(acc[0][ni], a[0][0], a[0][1], a[0][2], a[0][3], b0, b1);
                mma8(acc[1][ni], a[1][0], a[1][1], a[1][2], a[1][3], b0, b1);
            }
        }
        __syncthreads();
    }

    #pragma unroll
    for (int mi = 0; mi < 2; mi++) {
        #pragma unroll
        for (int ni = 0; ni < 4; ni++) {
            int lc = wn * 32 + ni * 8 + tig * 2;
            #pragma unroll
            for (int half = 0; half < 2; half++) {
                int r = rowBase + wm * 32 + mi * 16 + g + half * 8;
                if (r < NN) {
                    out[r * OUT_F + lc]     = acc[mi][ni][half * 2 + 0] + bm[lc];
                    out[r * OUT_F + lc + 1] = acc[mi][ni][half * 2 + 1] + bm[lc + 1];
                }
            }
        }
    }
}

// ---------------- launch ----------------
extern "C" void kernel_launch(void* const* d_in, const int* in_sizes, int n_in,
                              void* d_out, int out_size) {
    const float* x      = (const float*)d_in[0];
    const int*   ei     = (const int*)d_in[1];
    const float* W_gm   = (const float*)d_in[2];
    const float* b_gm   = (const float*)d_in[3];
    const float* W_gate = (const float*)d_in[4];
    const float* b_gate = (const float*)d_in[5];
    const float* W_fc   = (const float*)d_in[6];
    const float* attn_l = (const float*)d_in[7];
    const float* attn_r = (const float*)d_in[8];
    const float* b_gat  = (const float*)d_in[9];
    const float* W_mrg  = (const float*)d_in[10];
    const float* b_mrg  = (const float*)d_in[11];
    float* out = (float*)d_out;

    const int* src = ei;
    const int* dst = ei + EE;

    k_zero<<<(NN + 255) / 256, 256>>>();
    k_hist<<<(EE / 4 + 255) / 256, 256>>>(dst);
    k_scan1<<<NB, SCAN_BS>>>();
    k_gemm1<<<dim3((NN + 127) / 128, 5), 256>>>(x, W_gm, b_gm, W_fc);  // index 3: profiled
    k_scan2<<<1, 128>>>();
    k_scan3<<<NB, SCAN_BS>>>();
    k_scatter<<<(EE / 4 + 255) / 256, 256>>>(src, dst);
    k_pre<<<(NN + 7) / 8, 256>>>(x, attn_l, attn_r, W_gate);
    k_agg<<<(NN + 7) / 8, 256>>>(W_gate, b_gate, b_gat);
    k_merge<<<(NN + 127) / 128, 256>>>(x, W_mrg, b_mrg, out);
}

// round 8
// speedup vs baseline: 1.6943x; 1.0343x over previous
#include <cuda_runtime.h>
#include <cuda_fp16.h>

#define NN   50000
#define EE   800000
#define IN_F 128
#define OUT_F 64
#define MAPF 64
#define NH   4
#define SCAN_BS 512
#define NB ((NN + SCAN_BS - 1) / SCAN_BS)   // 98

// ---------------- scratch (static device globals; no allocation) ----------------
__device__ int   g_count[NN];
__device__ int   g_off[NN + 1];
__device__ int   g_cursor[NN];
__device__ int   g_bsum[NB];
__device__ int   g_bbase[NB];
__device__ int   g_srcs[EE];
__device__ unsigned g_zh[NN * 32];   // z as fp16: 64 halfs/row
__device__ uint2    g_fh[NN * 64];   // feat as fp16: 256 halfs/row ([h][64])
__device__ float4 g_eg[NN * 2];      // [2n] = el(4 heads), [2n+1] = gx3 = x@W_gate[192:320]
__device__ float4 g_er4[NN];         // er (4 heads)
__device__ float4 g_gx1[NN];         // x@W_gate[0:128]
__device__ float g_gated[NN * OUT_F];

// ---------------- helpers ----------------
__device__ __forceinline__ void hmma16(float* c, unsigned a0, unsigned a1, unsigned a2,
                                       unsigned a3, unsigned b0, unsigned b1) {
    asm volatile(
        "mma.sync.aligned.m16n8k16.row.col.f32.f16.f16.f32 "
        "{%0,%1,%2,%3},{%4,%5,%6,%7},{%8,%9},{%0,%1,%2,%3};"
        : "+f"(c[0]), "+f"(c[1]), "+f"(c[2]), "+f"(c[3])
        : "r"(a0), "r"(a1), "r"(a2), "r"(a3), "r"(b0), "r"(b1));
}
__device__ __forceinline__ unsigned packh2(float a, float b) {
    __half2 h = __floats2half2_rn(a, b);
    return *(unsigned*)&h;
}
__device__ __forceinline__ float2 unpackh2(unsigned u) {
    return __half22float2(*(__half2*)&u);
}

// ---------------- CSR build ----------------
__global__ void k_zero() {
    int i = blockIdx.x * blockDim.x + threadIdx.x;
    if (i < NN) g_count[i] = 0;
}

__global__ void k_hist(const int* __restrict__ dst) {
    int e4 = blockIdx.x * blockDim.x + threadIdx.x;
    if (e4 < EE / 4) {
        int4 d = ((const int4*)dst)[e4];
        atomicAdd(&g_count[d.x], 1);
        atomicAdd(&g_count[d.y], 1);
        atomicAdd(&g_count[d.z], 1);
        atomicAdd(&g_count[d.w], 1);
    }
}

__global__ void k_scan1() {
    __shared__ int wsum[16];
    int b = blockIdx.x, t = threadIdx.x, lane = t & 31, w = t >> 5;
    int i = b * SCAN_BS + t;
    int v = (i < NN) ? g_count[i] : 0;
    int xs = v;
    #pragma unroll
    for (int d = 1; d < 32; d <<= 1) {
        int y = __shfl_up_sync(0xffffffffu, xs, d);
        if (lane >= d) xs += y;
    }
    if (lane == 31) wsum[w] = xs;
    __syncthreads();
    if (w == 0) {
        int s = (lane < 16) ? wsum[lane] : 0;
        #pragma unroll
        for (int d = 1; d < 16; d <<= 1) {
            int y = __shfl_up_sync(0xffffffffu, s, d);
            if (lane >= d) s += y;
        }
        if (lane < 16) wsum[lane] = s;
    }
    __syncthreads();
    int base = (w > 0) ? wsum[w - 1] : 0;
    if (i < NN) g_off[i] = base + xs - v;
    if (t == SCAN_BS - 1) g_bsum[b] = wsum[15];
}

__global__ void k_scan2() {
    __shared__ int ws[4];
    int t = threadIdx.x, lane = t & 31, w = t >> 5;
    int v = (t < NB) ? g_bsum[t] : 0;
    int xs = v;
    #pragma unroll
    for (int d = 1; d < 32; d <<= 1) {
        int y = __shfl_up_sync(0xffffffffu, xs, d);
        if (lane >= d) xs += y;
    }
    if (lane == 31) ws[w] = xs;
    __syncthreads();
    if (t == 0) {
        int a = 0;
        #pragma unroll
        for (int k = 0; k < 4; k++) { int tmp = ws[k]; ws[k] = a; a += tmp; }
    }
    __syncthreads();
    if (t < NB) g_bbase[t] = ws[w] + xs - v;
}

__global__ void k_scan3() {
    int b = blockIdx.x, t = threadIdx.x;
    int i = b * SCAN_BS + t;
    if (i < NN) {
        int o = g_off[i] + g_bbase[b];
        g_off[i] = o;
        g_cursor[i] = o;
    }
    if (i == 0) g_off[NN] = EE;
}

__global__ void k_scatter(const int* __restrict__ src, const int* __restrict__ dst) {
    int e4 = blockIdx.x * blockDim.x + threadIdx.x;
    if (e4 < EE / 4) {
        int4 d = ((const int4*)dst)[e4];
        int4 s = ((const int4*)src)[e4];
        g_srcs[atomicAdd(&g_cursor[d.x], 1)] = s.x;
        g_srcs[atomicAdd(&g_cursor[d.y], 1)] = s.y;
        g_srcs[atomicAdd(&g_cursor[d.z], 1)] = s.z;
        g_srcs[atomicAdd(&g_cursor[d.w], 1)] = s.w;
    }
}

// ---------------- GEMM1 (fp16 HMMA m16n8k16): z_h (nt=0), feat_h (nt=1..4) -----------
// A: Ah[m][kk] = half2(x[m][2kk], x[m][2kk+1]); B: Bs[kk][n] = half2(W[2kk][n], W[2kk+1][n])
__global__ void k_gemm1(const float* __restrict__ x,
                        const float* __restrict__ Wgm, const float* __restrict__ bgm,
                        const float* __restrict__ Wfc) {
    __shared__ unsigned Ah[128][12];   // cols 0..7 used; stride 12 -> conflict-free frags
    __shared__ unsigned Bs[8][72];     // 64 n + pad 8 -> conflict-free frags
    int t = threadIdx.x;
    int nt = blockIdx.y;
    int rowBase = blockIdx.x * 128;
    const float* W; int ldw, colBase;
    if (nt == 0) { W = Wgm; ldw = 64;  colBase = 0; }
    else         { W = Wfc; ldw = 256; colBase = (nt - 1) * 64; }

    int lane = t & 31, wrp = t >> 5;
    int wm = wrp & 3, wn = wrp >> 2;
    int g = lane >> 2, tig = lane & 3;

    float acc[2][4][4];
    #pragma unroll
    for (int mi = 0; mi < 2; mi++)
        #pragma unroll
        for (int ni = 0; ni < 4; ni++)
            #pragma unroll
            for (int q = 0; q < 4; q++) acc[mi][ni][q] = 0.f;

    int ar0 = t >> 2, akq = t & 3;     // A loader: row 0..63(+64), k-quad 0..3
    int ar1 = ar0 + 64;
    int gr0 = rowBase + ar0; if (gr0 >= NN) gr0 = NN - 1;
    int gr1 = rowBase + ar1; if (gr1 >= NN) gr1 = NN - 1;
    int bkk = t >> 5, bl = t & 31;     // B loader: k-pair 0..7, n-pair 0..31
    int n2 = bl * 2;

    for (int kt = 0; kt < 8; kt++) {
        float4 a0v = *(const float4*)&x[gr0 * IN_F + kt * 16 + akq * 4];
        float4 a1v = *(const float4*)&x[gr1 * IN_F + kt * 16 + akq * 4];
        float2 bv0 = *(const float2*)&W[(kt * 16 + 2 * bkk) * ldw + colBase + n2];
        float2 bv1 = *(const float2*)&W[(kt * 16 + 2 * bkk + 1) * ldw + colBase + n2];
        uint2 ua0 = {packh2(a0v.x, a0v.y), packh2(a0v.z, a0v.w)};
        uint2 ua1 = {packh2(a1v.x, a1v.y), packh2(a1v.z, a1v.w)};
        uint2 ubv = {packh2(bv0.x, bv1.x), packh2(bv0.y, bv1.y)};
        *(uint2*)&Ah[ar0][akq * 2] = ua0;
        *(uint2*)&Ah[ar1][akq * 2] = ua1;
        *(uint2*)&Bs[bkk][n2]      = ubv;
        __syncthreads();
        unsigned a[2][4];
        #pragma unroll
        for (int mi = 0; mi < 2; mi++) {
            int rm = wm * 32 + mi * 16;
            a[mi][0] = Ah[rm + g][tig];
            a[mi][1] = Ah[rm + g + 8][tig];
            a[mi][2] = Ah[rm + g][tig + 4];
            a[mi][3] = Ah[rm + g + 8][tig + 4];
        }
        #pragma unroll
        for (int ni = 0; ni < 4; ni++) {
            int cn = wn * 32 + ni * 8;
            unsigned b0 = Bs[tig][cn + g];
            unsigned b1 = Bs[tig + 4][cn + g];
            hmma16(acc[0][ni], a[0][0], a[0][1], a[0][2], a[0][3], b0, b1);
            hmma16(acc[1][ni], a[1][0], a[1][1], a[1][2], a[1][3], b0, b1);
        }
        __syncthreads();
    }

    #pragma unroll
    for (int mi = 0; mi < 2; mi++) {
        #pragma unroll
        for (int ni = 0; ni < 4; ni++) {
            int lc = wn * 32 + ni * 8 + tig * 2;
            #pragma unroll
            for (int half = 0; half < 2; half++) {
                int r = rowBase + wm * 32 + mi * 16 + g + half * 8;
                if (r < NN) {
                    float v0 = acc[mi][ni][half * 2 + 0];
                    float v1 = acc[mi][ni][half * 2 + 1];
                    if (nt == 0) {
                        g_zh[r * 32 + (lc >> 1)] = packh2(v0 + bgm[lc], v1 + bgm[lc + 1]);
                    } else {
                        ((unsigned*)g_fh)[r * 128 + ((colBase + lc) >> 1)] = packh2(v0, v1);
                    }
                }
            }
        }
    }
}

// ---------------- k_pre: el/er + gx1/gx3 per node (warp per node) ----------------
__global__ void k_pre(const float* __restrict__ x,
                      const float* __restrict__ al, const float* __restrict__ ar,
                      const float* __restrict__ Wg) {
    __shared__ float sW1[IN_F * NH];   // W_gate rows 0..127
    __shared__ float sW3[IN_F * NH];   // W_gate rows 192..319
    for (int i = threadIdx.x; i < IN_F * NH; i += blockDim.x) {
        sW1[i] = Wg[i];
        sW3[i] = Wg[192 * NH + i];
    }
    __syncthreads();
    int w = threadIdx.x >> 5, lane = threadIdx.x & 31;
    int n = blockIdx.x * 8 + w;
    if (n >= NN) return;
    int h1 = lane >> 4, q = lane & 15;

    uint2 ua = g_fh[n * 64 + lane];
    uint2 ub = g_fh[n * 64 + 32 + lane];
    float2 fa0 = unpackh2(ua.x), fa1 = unpackh2(ua.y);
    float2 fb0 = unpackh2(ub.x), fb1 = unpackh2(ub.y);
    const float4* al4 = (const float4*)al;
    const float4* ar4 = (const float4*)ar;
    float4 a0 = al4[h1 * 16 + q], a1 = al4[(h1 + 2) * 16 + q];
    float4 r0 = ar4[h1 * 16 + q], r1 = ar4[(h1 + 2) * 16 + q];
    float el0 = fa0.x * a0.x + fa0.y * a0.y + fa1.x * a0.z + fa1.y * a0.w;
    float el1 = fb0.x * a1.x + fb0.y * a1.y + fb1.x * a1.z + fb1.y * a1.w;
    float er0 = fa0.x * r0.x + fa0.y * r0.y + fa1.x * r0.z + fa1.y * r0.w;
    float er1 = fb0.x * r1.x + fb0.y * r1.y + fb1.x * r1.z + fb1.y * r1.w;

    float4 xv = ((const float4*)x)[n * 32 + lane];
    float gx1[4], gx3[4];
    int r = 4 * lane;
    #pragma unroll
    for (int h = 0; h < 4; h++) {
        gx1[h] = xv.x * sW1[(r + 0) * 4 + h] + xv.y * sW1[(r + 1) * 4 + h]
               + xv.z * sW1[(r + 2) * 4 + h] + xv.w * sW1[(r + 3) * 4 + h];
        gx3[h] = xv.x * sW3[(r + 0) * 4 + h] + xv.y * sW3[(r + 1) * 4 + h]
               + xv.z * sW3[(r + 2) * 4 + h] + xv.w * sW3[(r + 3) * 4 + h];
    }

    #pragma unroll
    for (int d = 8; d >= 1; d >>= 1) {
        el0 += __shfl_down_sync(0xffffffffu, el0, d);
        el1 += __shfl_down_sync(0xffffffffu, el1, d);
        er0 += __shfl_down_sync(0xffffffffu, er0, d);
        er1 += __shfl_down_sync(0xffffffffu, er1, d);
    }
    #pragma unroll
    for (int d = 16; d >= 1; d >>= 1) {
        #pragma unroll
        for (int h = 0; h < 4; h++) {
            gx1[h] += __shfl_xor_sync(0xffffffffu, gx1[h], d);
            gx3[h] += __shfl_xor_sync(0xffffffffu, gx3[h], d);
        }
    }
    float elh1 = __shfl_sync(0xffffffffu, el0, 16);
    float elh3 = __shfl_sync(0xffffffffu, el1, 16);
    float erh1 = __shfl_sync(0xffffffffu, er0, 16);
    float erh3 = __shfl_sync(0xffffffffu, er1, 16);
    if (lane == 0) {
        g_eg[2 * n]     = make_float4(el0, elh1, el1, elh3);
        g_eg[2 * n + 1] = make_float4(gx3[0], gx3[1], gx3[2], gx3[3]);
        g_er4[n]        = make_float4(er0, erh1, er1, erh3);
        g_gx1[n]        = make_float4(gx1[0], gx1[1], gx1[2], gx1[3]);
    }
}

// ---------------- fused single-pass agg, unroll-4 + src-index software pipeline -------
__global__ void k_agg(const float* __restrict__ Wg, const float* __restrict__ bg,
                      const float* __restrict__ bgat) {
    __shared__ float sW2[MAPF * NH];   // W_gate rows 128..191
    for (int i = threadIdx.x; i < MAPF * NH; i += blockDim.x) sW2[i] = Wg[IN_F * NH + i];
    __syncthreads();
    int w = threadIdx.x >> 5, lane = threadIdx.x & 31;
    int d = blockIdx.x * 8 + w;
    if (d >= NN) return;
    int o0 = g_off[d], o1 = g_off[d + 1];
    int deg = o1 - o0;

    float4 er4 = g_er4[d];
    float4 gx1d = g_gx1[d];
    int h1 = lane >> 4, q = lane & 15;

    float zmx = -1e30f, zmy = -1e30f;
    float gxs0 = 0.f, gxs1 = 0.f, gxs2 = 0.f, gxs3 = 0.f;
    float den0 = 0.f, den1 = 0.f, den2 = 0.f, den3 = 0.f;
    float4 acc0 = {0.f, 0.f, 0.f, 0.f}, acc1 = {0.f, 0.f, 0.f, 0.f};

    int i = o0;
    if (deg >= 4) {
        int last = o1 - 1;
        // pipeline prologue: preload first 4 indices
        int p0 = g_srcs[i], p1 = g_srcs[i + 1], p2 = g_srcs[i + 2], p3 = g_srcs[i + 3];
        for (; i + 3 < o1; i += 4) {
            int s[4] = {p0, p1, p2, p3};
            unsigned zu[4]; float4 ev[4], g3[4]; uint2 ua[4], ub[4];
            #pragma unroll
            for (int j = 0; j < 4; j++) {
                zu[j] = g_zh[s[j] * 32 + lane];
                ev[j] = g_eg[2 * s[j]];
                g3[j] = g_eg[2 * s[j] + 1];
                ua[j] = g_fh[s[j] * 64 + lane];
                ub[j] = g_fh[s[j] * 64 + 32 + lane];
            }
            // prefetch next iteration's indices (clamped; harmless dup loads at tail)
            int nb = i + 4;
            p0 = g_srcs[min(nb,     last)];
            p1 = g_srcs[min(nb + 1, last)];
            p2 = g_srcs[min(nb + 2, last)];
            p3 = g_srcs[min(nb + 3, last)];
            #pragma unroll
            for (int j = 0; j < 4; j++) {
                float2 zv = unpackh2(zu[j]);
                zmx = fmaxf(zmx, zv.x); zmy = fmaxf(zmy, zv.y);
                gxs0 += g3[j].x; gxs1 += g3[j].y; gxs2 += g3[j].z; gxs3 += g3[j].w;
                float e0 = ev[j].x + er4.x, e1 = ev[j].y + er4.y;
                float e2 = ev[j].z + er4.z, e3 = ev[j].w + er4.w;
                e0 = (e0 > 0.f) ? e0 : 0.2f * e0;
                e1 = (e1 > 0.f) ? e1 : 0.2f * e1;
                e2 = (e2 > 0.f) ? e2 : 0.2f * e2;
                e3 = (e3 > 0.f) ? e3 : 0.2f * e3;
                float w0 = __expf(e0), w1 = __expf(e1);
                float w2 = __expf(e2), w3 = __expf(e3);
                den0 += w0; den1 += w1; den2 += w2; den3 += w3;
                float2 fa0 = unpackh2(ua[j].x), fa1 = unpackh2(ua[j].y);
                float2 fb0 = unpackh2(ub[j].x), fb1 = unpackh2(ub[j].y);
                float wa = (h1 == 0) ? w0 : w1;
                float wb = (h1 == 0) ? w2 : w3;
                acc0.x += wa * fa0.x; acc0.y += wa * fa0.y; acc0.z += wa * fa1.x; acc0.w += wa * fa1.y;
                acc1.x += wb * fb0.x; acc1.y += wb * fb0.y; acc1.z += wb * fb1.x; acc1.w += wb * fb1.y;
            }
        }
    }
    for (; i < o1; i++) {
        int s0 = g_srcs[i];
        unsigned zu0 = g_zh[s0 * 32 + lane];
        float4 ev0 = g_eg[2 * s0];
        float4 g30 = g_eg[2 * s0 + 1];
        uint2 ua0 = g_fh[s0 * 64 + lane];
        uint2 ub0 = g_fh[s0 * 64 + 32 + lane];
        float2 zv = unpackh2(zu0);
        zmx = fmaxf(zmx, zv.x); zmy = fmaxf(zmy, zv.y);
        gxs0 += g30.x; gxs1 += g30.y; gxs2 += g30.z; gxs3 += g30.w;
        float e0 = ev0.x + er4.x, e1 = ev0.y + er4.y;
        float e2 = ev0.z + er4.z, e3 = ev0.w + er4.w;
        e0 = (e0 > 0.f) ? e0 : 0.2f * e0;
        e1 = (e1 > 0.f) ? e1 : 0.2f * e1;
        e2 = (e2 > 0.f) ? e2 : 0.2f * e2;
        e3 = (e3 > 0.f) ? e3 : 0.2f * e3;
        float w0 = __expf(e0), w1 = __expf(e1);
        float w2 = __expf(e2), w3 = __expf(e3);
        den0 += w0; den1 += w1; den2 += w2; den3 += w3;
        float2 fa0 = unpackh2(ua0.x), fa1 = unpackh2(ua0.y);
        float2 fb0 = unpackh2(ub0.x), fb1 = unpackh2(ub0.y);
        float wa = (h1 == 0) ? w0 : w1;
        float wb = (h1 == 0) ? w2 : w3;
        acc0.x += wa * fa0.x; acc0.y += wa * fa0.y; acc0.z += wa * fa1.x; acc0.w += wa * fa1.y;
        acc1.x += wb * fb0.x; acc1.y += wb * fb0.y; acc1.z += wb * fb1.x; acc1.w += wb * fb1.y;
    }

    // ---- gate ----
    float inv = (deg > 0) ? 1.0f / (float)deg : 0.0f;
    if (deg == 0) { zmx = 0.f; zmy = 0.f; }
    float zr[4];
    int r2 = 2 * lane;
    #pragma unroll
    for (int h = 0; h < 4; h++)
        zr[h] = zmx * sW2[(r2 + 0) * 4 + h] + zmy * sW2[(r2 + 1) * 4 + h];
    #pragma unroll
    for (int dd = 16; dd >= 1; dd >>= 1) {
        #pragma unroll
        for (int h = 0; h < 4; h++) zr[h] += __shfl_xor_sync(0xffffffffu, zr[h], dd);
    }
    float gxs[4] = {gxs0, gxs1, gxs2, gxs3};
    float gx1a[4] = {gx1d.x, gx1d.y, gx1d.z, gx1d.w};
    float gate[4];
    #pragma unroll
    for (int h = 0; h < 4; h++) {
        float p = gx1a[h] + gxs[h] * inv + zr[h] + bg[h];
        gate[h] = 1.f / (1.f + __expf(-p));
    }

    // ---- normalize, bias, gate, head-average, store ----
    float4 bga = ((const float4*)bgat)[h1 * 16 + q];
    float4 bgb = ((const float4*)bgat)[(h1 + 2) * 16 + q];
    float4 a0, a1;
    if (deg > 0) {
        float ia = 1.f / ((h1 == 0) ? den0 : den1);
        float ib = 1.f / ((h1 == 0) ? den2 : den3);
        a0.x = acc0.x * ia + bga.x; a0.y = acc0.y * ia + bga.y;
        a0.z = acc0.z * ia + bga.z; a0.w = acc0.w * ia + bga.w;
        a1.x = acc1.x * ib + bgb.x; a1.y = acc1.y * ib + bgb.y;
        a1.z = acc1.z * ib + bgb.z; a1.w = acc1.w * ib + bgb.w;
    } else {
        a0 = bga; a1 = bgb;
    }
    float g0 = (h1 == 0) ? gate[0] : gate[1];
    float g1 = (h1 == 0) ? gate[2] : gate[3];
    float4 pp;
    pp.x = g0 * a0.x + g1 * a1.x;
    pp.y = g0 * a0.y + g1 * a1.y;
    pp.z = g0 * a0.z + g1 * a1.z;
    pp.w = g0 * a0.w + g1 * a1.w;
    pp.x += __shfl_xor_sync(0xffffffffu, pp.x, 16);
    pp.y += __shfl_xor_sync(0xffffffffu, pp.y, 16);
    pp.z += __shfl_xor_sync(0xffffffffu, pp.z, 16);
    pp.w += __shfl_xor_sync(0xffffffffu, pp.w, 16);
    pp.x *= 0.25f; pp.y *= 0.25f; pp.z *= 0.25f; pp.w *= 0.25f;
    if (lane < 16) ((float4*)g_gated)[d * 16 + lane] = pp;
}

// ---------------- merge GEMM (fp16 HMMA): out = [x | gated] @ W_merge + b_merge -------
__global__ void k_merge(const float* __restrict__ x, const float* __restrict__ Wm,
                        const float* __restrict__ bm, float* __restrict__ out) {
    __shared__ unsigned Ah[128][12];
    __shared__ unsigned Bs[8][72];
    int t = threadIdx.x;
    int rowBase = blockIdx.x * 128;
    int lane = t & 31, wrp = t >> 5;
    int wm = wrp & 3, wn = wrp >> 2;
    int g = lane >> 2, tig = lane & 3;

    float acc[2][4][4];
    #pragma unroll
    for (int mi = 0; mi < 2; mi++)
        #pragma unroll
        for (int ni = 0; ni < 4; ni++)
            #pragma unroll
            for (int q = 0; q < 4; q++) acc[mi][ni][q] = 0.f;

    int ar0 = t >> 2, akq = t & 3;
    int ar1 = ar0 + 64;
    int gr0 = rowBase + ar0; if (gr0 >= NN) gr0 = NN - 1;
    int gr1 = rowBase + ar1; if (gr1 >= NN) gr1 = NN - 1;
    int bkk = t >> 5, bl = t & 31;
    int n2 = bl * 2;

    for (int kt = 0; kt < 12; kt++) {
        int k0 = kt * 16 + akq * 4;
        float4 a0v, a1v;
        if (k0 < IN_F) {
            a0v = *(const float4*)&x[gr0 * IN_F + k0];
            a1v = *(const float4*)&x[gr1 * IN_F + k0];
        } else {
            a0v = *(const float4*)&g_gated[gr0 * OUT_F + (k0 - IN_F)];
            a1v = *(const float4*)&g_gated[gr1 * OUT_F + (k0 - IN_F)];
        }
        float2 bv0 = *(const float2*)&Wm[(kt * 16 + 2 * bkk) * 64 + n2];
        float2 bv1 = *(const float2*)&Wm[(kt * 16 + 2 * bkk + 1) * 64 + n2];
        uint2 ua0 = {packh2(a0v.x, a0v.y), packh2(a0v.z, a0v.w)};
        uint2 ua1 = {packh2(a1v.x, a1v.y), packh2(a1v.z, a1v.w)};
        uint2 ubv = {packh2(bv0.x, bv1.x), packh2(bv0.y, bv1.y)};
        *(uint2*)&Ah[ar0][akq * 2] = ua0;
        *(uint2*)&Ah[ar1][akq * 2] = ua1;
        *(uint2*)&Bs[bkk][n2]      = ubv;
        __syncthreads();
        unsigned a[2][4];
        #pragma unroll
        for (int mi = 0; mi < 2; mi++) {
            int rm = wm * 32 + mi * 16;
            a[mi][0] = Ah[rm + g][tig];
            a[mi][1] = Ah[rm + g + 8][tig];
            a[mi][2] = Ah[rm + g][tig + 4];
            a[mi][3] = Ah[rm + g + 8][tig + 4];
        }
        #pragma unroll
        for (int ni = 0; ni < 4; ni++) {
            int cn = wn * 32 + ni * 8;
            unsigned b0 = Bs[tig][cn + g];
            unsigned b1 = Bs[tig + 4][cn + g];
            hmma16(acc[0][ni], a[0][0], a[0][1], a[0][2], a[0][3], b0, b1);
            hmma16(acc[1][ni], a[1][0], a[1][1], a[1][2], a[1][3], b0, b1);
        }
        __syncthreads();
    }

    #pragma unroll
    for (int mi = 0; mi < 2; mi++) {
        #pragma unroll
        for (int ni = 0; ni < 4; ni++) {
            int lc = wn * 32 + ni * 8 + tig * 2;
            #pragma unroll
            for (int half = 0; half < 2; half++) {
                int r = rowBase + wm * 32 + mi * 16 + g + half * 8;
                if (r < NN) {
                    out[r * OUT_F + lc]     = acc[mi][ni][half * 2 + 0] + bm[lc];
                    out[r * OUT_F + lc + 1] = acc[mi][ni][half * 2 + 1] + bm[lc + 1];
                }
            }
        }
    }
}

// ---------------- launch ----------------
extern "C" void kernel_launch(void* const* d_in, const int* in_sizes, int n_in,
                              void* d_out, int out_size) {
    const float* x      = (const float*)d_in[0];
    const int*   ei     = (const int*)d_in[1];
    const float* W_gm   = (const float*)d_in[2];
    const float* b_gm   = (const float*)d_in[3];
    const float* W_gate = (const float*)d_in[4];
    const float* b_gate = (const float*)d_in[5];
    const float* W_fc   = (const float*)d_in[6];
    const float* attn_l = (const float*)d_in[7];
    const float* attn_r = (const float*)d_in[8];
    const float* b_gat  = (const float*)d_in[9];
    const float* W_mrg  = (const float*)d_in[10];
    const float* b_mrg  = (const float*)d_in[11];
    float* out = (float*)d_out;

    const int* src = ei;
    const int* dst = ei + EE;

    k_zero<<<(NN + 255) / 256, 256>>>();
    k_hist<<<(EE / 4 + 255) / 256, 256>>>(dst);
    k_scan1<<<NB, SCAN_BS>>>();
    k_gemm1<<<dim3((NN + 127) / 128, 5), 256>>>(x, W_gm, b_gm, W_fc);  // index 3: profiled
    k_scan2<<<1, 128>>>();
    k_scan3<<<NB, SCAN_BS>>>();
    k_scatter<<<(EE / 4 + 255) / 256, 256>>>(src, dst);
    k_pre<<<(NN + 7) / 8, 256>>>(x, attn_l, attn_r, W_gate);
    k_agg<<<(NN + 7) / 8, 256>>>(W_gate, b_gate, b_gat);
    k_merge<<<(NN + 127) / 128, 256>>>(x, W_mrg, b_mrg, out);
}